// round 6
// baseline (speedup 1.0000x reference)
#include <cuda_runtime.h>
#include <cstdint>

#define NN 50000
#define EMAX 500000
#define HID 160

// ---------------- scratch (static device globals; no allocation) ----------------
__device__ float g_feat[NN * HID];
__device__ float g_h1[NN * HID];
__device__ float g_mean[NN * HID];
__device__ float g_h2[NN * HID];
__device__ int g_deg[NN];
__device__ int g_offs[NN + 1];
__device__ int g_cursor[NN];
__device__ int g_csr[EMAX];
__device__ int g_is64;
// tf32-preconverted weights: W_des | W_tw | W_txt | W_in | W_l | W_r | W_o1
__device__ uint32_t g_wtf[3 * 24576 + 4 * 25600];

__device__ __forceinline__ float lrelu(float x) { return x > 0.f ? x : 0.01f * x; }

__device__ __forceinline__ uint32_t f2tf32(float x) {
    uint32_t u;
    asm("cvt.rna.tf32.f32 %0, %1;" : "=r"(u) : "f"(x));
    return u;
}

__device__ __forceinline__ void cp16(void* dst_smem, const void* src, bool pred) {
    uint32_t d = (uint32_t)__cvta_generic_to_shared(dst_smem);
    int sz = pred ? 16 : 0;
    asm volatile("cp.async.cg.shared.global [%0], [%1], 16, %2;" :: "r"(d), "l"(src), "r"(sz));
}

// ---------------- weight preconversion (fp32 -> tf32 bits, RNA) ----------------
struct WConvArgs {
    const float* src[7];
    int off[8];
};

__global__ void wconv_kernel(WConvArgs a) {
    int i = blockIdx.x * 256 + threadIdx.x;
    #pragma unroll
    for (int s = 0; s < 7; s++) {
        if (i >= a.off[s] && i < a.off[s + 1])
            g_wtf[i] = f2tf32(a.src[s][i - a.off[s]]);
    }
}

// Edge index may be int64 (reference) or int32 (JAX canonicalization).
__device__ __forceinline__ int edge_val(const void* ei, int idx) {
    if (g_is64) return (int)((const long long*)ei)[idx];
    return ((const int*)ei)[idx];
}

__global__ void detect_kernel(const void* ei, int E) {
    __shared__ int any_hi;
    int t = threadIdx.x;
    if (t == 0) any_hi = 0;
    __syncthreads();
    const unsigned long long* p = (const unsigned long long*)ei;
    int n = E < 1024 ? E : 1024;
    unsigned long long acc = 0;
    for (int i = t; i < n; i += 256) acc |= p[i];
    if (acc > 0xFFFFFFFFull) atomicOr(&any_hi, 1);
    __syncthreads();
    if (t == 0) g_is64 = any_hi ? 0 : 1;
}

// ============ HID GEMM: BM=64, BN=160 (full width), BK=32 ============
// 256 threads = 8 warps = 2 m-warps x 4 n-warps; warp tile 32m x 40n.
// A read ONCE from L2 (no grid.y). W preconverted tf32. Dynamic smem 61,440B.
#define AS_WORDS (2 * 64 * 36)
#define WS_WORDS (2 * 32 * 168)
#define HIDSMEM ((AS_WORDS + WS_WORDS) * 4)

template <bool LEAKY>
__global__ void __launch_bounds__(256, 3) hid_gemm(
    const float* __restrict__ A1, const uint32_t* __restrict__ W1,
    const float* __restrict__ A2, const uint32_t* __restrict__ W2,
    const float* __restrict__ bias, float* __restrict__ C,
    int M, int K, bool dual)
{
    extern __shared__ __align__(16) char smraw[];
    // As[buf][m][k] stride 36: frag bank = (4m + k) % 32, conflict-free.
    // Ws[buf][k][n] stride 168 (≡8 mod 32): frag bank = (8k + n) % 32, conflict-free.
    float (*As)[64][36] = reinterpret_cast<float (*)[64][36]>(smraw);
    uint32_t (*Ws)[32][168] = reinterpret_cast<uint32_t (*)[32][168]>(smraw + AS_WORDS * 4);

    const int t = threadIdx.x;
    const int warp = t >> 5;
    const int lane = t & 31;
    const int mwarp = warp >> 2;       // 0..1
    const int nwarp = warp & 3;        // 0..3
    const int g = lane >> 2;
    const int tg = lane & 3;
    const int blockRow = blockIdx.x * 64;
    const int warpRow = mwarp * 32;
    const int ncol0 = nwarp * 40;

    // A loader: thread t -> row t>>2 (0..63), col (t&3)*8, 2x cp16
    const int arow = t >> 2;
    const int acol = (t & 3) * 8;
    // W loader: thread t -> k-row t>>3 (0..31), col (t&7)*20, 5x cp16
    const int wrow = t >> 3;
    const int wcol = (t & 7) * 20;

    const int nkpp = K >> 5;
    const int nchunks = dual ? (nkpp << 1) : nkpp;

    auto issue = [&](int c) {
        int pass = (c >= nkpp) ? 1 : 0;
        int k0 = (pass ? c - nkpp : c) << 5;
        const float* __restrict__ A = pass ? A2 : A1;
        const uint32_t* __restrict__ W = pass ? W2 : W1;
        int buf = c & 1;
        int gr = blockRow + arow;
        const float* src = A + (size_t)gr * K + k0 + acol;
        bool p = gr < M;
        cp16(&As[buf][arow][acol], src, p);
        cp16(&As[buf][arow][acol + 4], src + 4, p);
        const uint32_t* wsrc = W + (size_t)(k0 + wrow) * HID + wcol;
        #pragma unroll
        for (int j = 0; j < 5; j++)
            cp16(&Ws[buf][wrow][wcol + j * 4], wsrc + j * 4, true);
        asm volatile("cp.async.commit_group;");
    };

    float acc[2][5][4] = {};

    issue(0);
    for (int c = 0; c < nchunks; c++) {
        if (c + 1 < nchunks) {
            issue(c + 1);
            asm volatile("cp.async.wait_group 1;");
        } else {
            asm volatile("cp.async.wait_group 0;");
        }
        __syncthreads();
        const int buf = c & 1;
        #pragma unroll
        for (int kk = 0; kk < 32; kk += 8) {
            uint32_t a[2][4];
            #pragma unroll
            for (int mt = 0; mt < 2; mt++) {
                const int r = warpRow + mt * 16 + g;
                a[mt][0] = f2tf32(As[buf][r][kk + tg]);
                a[mt][1] = f2tf32(As[buf][r + 8][kk + tg]);
                a[mt][2] = f2tf32(As[buf][r][kk + tg + 4]);
                a[mt][3] = f2tf32(As[buf][r + 8][kk + tg + 4]);
            }
            #pragma unroll
            for (int nt = 0; nt < 5; nt++) {
                uint32_t b0 = Ws[buf][kk + tg][ncol0 + nt * 8 + g];
                uint32_t b1 = Ws[buf][kk + tg + 4][ncol0 + nt * 8 + g];
                #pragma unroll
                for (int mt = 0; mt < 2; mt++) {
                    float* cc = acc[mt][nt];
                    asm volatile(
                        "mma.sync.aligned.m16n8k8.row.col.f32.tf32.tf32.f32 "
                        "{%0,%1,%2,%3}, {%4,%5,%6,%7}, {%8,%9}, {%0,%1,%2,%3};"
                        : "+f"(cc[0]), "+f"(cc[1]), "+f"(cc[2]), "+f"(cc[3])
                        : "r"(a[mt][0]), "r"(a[mt][1]), "r"(a[mt][2]), "r"(a[mt][3]),
                          "r"(b0), "r"(b1));
                }
            }
        }
        __syncthreads();
    }

    // ---- epilogue ----
    #pragma unroll
    for (int nt = 0; nt < 5; nt++) {
        int lc = ncol0 + nt * 8 + 2 * tg;
        float b0 = bias[lc];
        float b1 = bias[lc + 1];
        #pragma unroll
        for (int mt = 0; mt < 2; mt++) {
            float* cc = acc[mt][nt];
            int r0 = blockRow + warpRow + mt * 16 + g;
            int r1 = r0 + 8;
            float v00 = cc[0] + b0, v01 = cc[1] + b1;
            float v10 = cc[2] + b0, v11 = cc[3] + b1;
            if (LEAKY) {
                v00 = lrelu(v00); v01 = lrelu(v01);
                v10 = lrelu(v10); v11 = lrelu(v11);
            }
            if (r0 < M)
                *(float2*)(C + (size_t)r0 * HID + lc) = make_float2(v00, v01);
            if (r1 < M)
                *(float2*)(C + (size_t)r1 * HID + lc) = make_float2(v10, v11);
        }
    }
}

// ============ projection GEMM (BN=32 output): round-5 split-K core ============
// BM=128, BN=32, BK=32; 256 threads = 4 m-warps x 2 k-groups; warp 32m x 32n.
struct ProjArgs {
    const float* A[3];
    const uint32_t* W[3];
    const float* b[3];
    int off[3];
};

__global__ void __launch_bounds__(256) proj_kernel(ProjArgs pa, float* __restrict__ C,
                                                   int M, int K)
{
    __shared__ __align__(16) float As[2][128][36];
    __shared__ __align__(16) uint32_t Ws[2][32][40];

    const int z = blockIdx.z;
    const float* __restrict__ A = pa.A[z];
    const uint32_t* __restrict__ W = pa.W[z];
    const float* __restrict__ bias = pa.b[z];
    const int cOff = pa.off[z];

    const int t = threadIdx.x;
    const int warp = t >> 5;
    const int lane = t & 31;
    const int mwarp = warp & 3;
    const int kg = warp >> 2;
    const int g = lane >> 2;
    const int tg = lane & 3;
    const int blockRow = blockIdx.x * 128;
    const int warpRow = mwarp * 32;

    const int arow = t >> 1;
    const int acol = (t & 1) * 16;
    const int wrow = t >> 3;
    const int wcol = (t & 7) * 4;

    const int nchunks = K >> 5;

    auto issue = [&](int c) {
        int k0 = c << 5;
        int buf = c & 1;
        int gr = blockRow + arow;
        const float* src = A + (size_t)gr * K + k0 + acol;
        bool p = gr < M;
        #pragma unroll
        for (int j = 0; j < 4; j++)
            cp16(&As[buf][arow][acol + j * 4], src + j * 4, p);
        const uint32_t* wsrc = W + (size_t)(k0 + wrow) * 32 + wcol;
        cp16(&Ws[buf][wrow][wcol], wsrc, true);
        asm volatile("cp.async.commit_group;");
    };

    float acc[2][4][4] = {};

    issue(0);
    for (int c = 0; c < nchunks; c++) {
        if (c + 1 < nchunks) {
            issue(c + 1);
            asm volatile("cp.async.wait_group 1;");
        } else {
            asm volatile("cp.async.wait_group 0;");
        }
        __syncthreads();
        const int buf = c & 1;
        #pragma unroll
        for (int s = 0; s < 2; s++) {
            const int kk = kg * 16 + s * 8;
            uint32_t a[2][4];
            #pragma unroll
            for (int mt = 0; mt < 2; mt++) {
                const int r = warpRow + mt * 16 + g;
                a[mt][0] = f2tf32(As[buf][r][kk + tg]);
                a[mt][1] = f2tf32(As[buf][r + 8][kk + tg]);
                a[mt][2] = f2tf32(As[buf][r][kk + tg + 4]);
                a[mt][3] = f2tf32(As[buf][r + 8][kk + tg + 4]);
            }
            #pragma unroll
            for (int nt = 0; nt < 4; nt++) {
                uint32_t b0 = Ws[buf][kk + tg][nt * 8 + g];
                uint32_t b1 = Ws[buf][kk + tg + 4][nt * 8 + g];
                #pragma unroll
                for (int mt = 0; mt < 2; mt++) {
                    float* cc = acc[mt][nt];
                    asm volatile(
                        "mma.sync.aligned.m16n8k8.row.col.f32.tf32.tf32.f32 "
                        "{%0,%1,%2,%3}, {%4,%5,%6,%7}, {%8,%9}, {%0,%1,%2,%3};"
                        : "+f"(cc[0]), "+f"(cc[1]), "+f"(cc[2]), "+f"(cc[3])
                        : "r"(a[mt][0]), "r"(a[mt][1]), "r"(a[mt][2]), "r"(a[mt][3]),
                          "r"(b0), "r"(b1));
                }
            }
        }
        __syncthreads();
    }

    float* scratch = &As[0][0][0];
    if (kg == 1) {
        #pragma unroll
        for (int mt = 0; mt < 2; mt++)
            #pragma unroll
            for (int nt = 0; nt < 4; nt++)
                #pragma unroll
                for (int i = 0; i < 4; i++) {
                    int combo = (mt * 4 + nt) * 4 + i;
                    scratch[combo * 128 + mwarp * 32 + lane] = acc[mt][nt][i];
                }
    }
    __syncthreads();

    if (kg == 0) {
        #pragma unroll
        for (int nt = 0; nt < 4; nt++) {
            int lc = nt * 8 + 2 * tg;
            float b0 = bias[lc];
            float b1 = bias[lc + 1];
            #pragma unroll
            for (int mt = 0; mt < 2; mt++) {
                float* cc = acc[mt][nt];
                int base = ((mt * 4 + nt) * 4) * 128 + mwarp * 32 + lane;
                float v00 = cc[0] + scratch[base]       + b0;
                float v01 = cc[1] + scratch[base + 128] + b1;
                float v10 = cc[2] + scratch[base + 256] + b0;
                float v11 = cc[3] + scratch[base + 384] + b1;
                v00 = lrelu(v00); v01 = lrelu(v01);
                v10 = lrelu(v10); v11 = lrelu(v11);
                int r0 = blockRow + warpRow + mt * 16 + g;
                int r1 = r0 + 8;
                if (r0 < M)
                    *(float2*)(C + (size_t)r0 * HID + cOff + lc) = make_float2(v00, v01);
                if (r1 < M)
                    *(float2*)(C + (size_t)r1 * HID + cOff + lc) = make_float2(v10, v11);
            }
        }
    }
}

// ---------------- small feature projections: num_prop (6->32), num_category (11->32)
__global__ void __launch_bounds__(256) feat_small_kernel(
    const float* __restrict__ np, const float* __restrict__ nc,
    const float* __restrict__ Wnp, const float* __restrict__ bnp,
    const float* __restrict__ Wnc, const float* __restrict__ bnc,
    float* __restrict__ out)
{
    __shared__ float sWnp[6 * 32];
    __shared__ float sWnc[11 * 32];
    __shared__ float sb[64];
    int t = threadIdx.x;
    for (int i = t; i < 192; i += 256) sWnp[i] = Wnp[i];
    for (int i = t; i < 352; i += 256) sWnc[i] = Wnc[i];
    if (t < 32) sb[t] = bnp[t];
    else if (t < 64) sb[t] = bnc[t - 32];
    __syncthreads();

    int node = blockIdx.x * 8 + (t >> 5);
    int lane = t & 31;
    if (node >= NN) return;

    float a = sb[lane], c = sb[32 + lane];
    #pragma unroll
    for (int k = 0; k < 6; k++) a += np[(size_t)node * 6 + k] * sWnp[k * 32 + lane];
    #pragma unroll
    for (int k = 0; k < 11; k++) c += nc[(size_t)node * 11 + k] * sWnc[k * 32 + lane];
    out[(size_t)node * HID + lane] = lrelu(a);
    out[(size_t)node * HID + 32 + lane] = lrelu(c);
}

// ---------------- CSR build ----------------
__global__ void zero_deg_kernel() {
    int i = blockIdx.x * blockDim.x + threadIdx.x;
    if (i < NN) g_deg[i] = 0;
}

__global__ void count_deg_kernel(const void* __restrict__ ei, int E) {
    int e = blockIdx.x * blockDim.x + threadIdx.x;
    if (e < E) atomicAdd(&g_deg[edge_val(ei, E + e)], 1);
}

__global__ void scan_kernel() {
    __shared__ int part[1024];
    int t = threadIdx.x;
    const int chunk = (NN + 1023) / 1024;
    int s0 = t * chunk;
    int s1 = s0 + chunk; if (s1 > NN) s1 = NN; if (s0 > NN) s0 = NN;
    int s = 0;
    for (int i = s0; i < s1; i++) s += g_deg[i];
    part[t] = s;
    __syncthreads();
    for (int d = 1; d < 1024; d <<= 1) {
        int v = (t >= d) ? part[t - d] : 0;
        __syncthreads();
        part[t] += v;
        __syncthreads();
    }
    int excl = t ? part[t - 1] : 0;
    for (int i = s0; i < s1; i++) {
        g_offs[i] = excl;
        g_cursor[i] = excl;
        excl += g_deg[i];
    }
    if (t == 1023) g_offs[NN] = part[1023];
}

__global__ void fill_csr_kernel(const void* __restrict__ ei, int E) {
    int e = blockIdx.x * blockDim.x + threadIdx.x;
    if (e < E) {
        int d = edge_val(ei, E + e);
        int p = atomicAdd(&g_cursor[d], 1);
        g_csr[p] = edge_val(ei, e);
    }
}

// ---------------- mean aggregation: one warp per node ----------------
__global__ void __launch_bounds__(256) agg_kernel(const float* __restrict__ h,
                                                  float* __restrict__ mean)
{
    int w = (blockIdx.x * blockDim.x + threadIdx.x) >> 5;
    int lane = threadIdx.x & 31;
    if (w >= NN) return;
    int beg = g_offs[w], end = g_offs[w + 1];
    float a0 = 0.f, a1 = 0.f, a2 = 0.f, a3 = 0.f, a4 = 0.f;
    for (int e = beg; e < end; e++) {
        const float* row = h + (size_t)g_csr[e] * HID;
        a0 += row[lane];
        a1 += row[lane + 32];
        a2 += row[lane + 64];
        a3 += row[lane + 96];
        a4 += row[lane + 128];
    }
    int deg = end - beg;
    float inv = 1.f / (float)(deg > 0 ? deg : 1);
    float* m = mean + (size_t)w * HID;
    m[lane]       = a0 * inv;
    m[lane + 32]  = a1 * inv;
    m[lane + 64]  = a2 * inv;
    m[lane + 96]  = a3 * inv;
    m[lane + 128] = a4 * inv;
}

// ---------------- final 160->2 head: one warp per node ----------------
__global__ void __launch_bounds__(256) out2_kernel(
    const float* __restrict__ em, const float* __restrict__ W,
    const float* __restrict__ b, float* __restrict__ out)
{
    __shared__ float sW[320];
    int t = threadIdx.x;
    for (int i = t; i < 320; i += 256) sW[i] = W[i];
    __syncthreads();
    int node = blockIdx.x * 8 + (t >> 5);
    int lane = t & 31;
    if (node >= NN) return;
    float a0 = 0.f, a1 = 0.f;
    #pragma unroll
    for (int c = 0; c < 5; c++) {
        int k = lane + 32 * c;
        float v = em[(size_t)node * HID + k];
        a0 += v * sW[k * 2];
        a1 += v * sW[k * 2 + 1];
    }
    #pragma unroll
    for (int o = 16; o > 0; o >>= 1) {
        a0 += __shfl_down_sync(0xffffffffu, a0, o);
        a1 += __shfl_down_sync(0xffffffffu, a1, o);
    }
    if (lane == 0) {
        out[(size_t)node * 2]     = a0 + b[0];
        out[(size_t)node * 2 + 1] = a1 + b[1];
    }
}

// ---------------- launch ----------------
extern "C" void kernel_launch(void* const* d_in, const int* in_sizes, int n_in,
                              void* d_out, int out_size)
{
    const float* x        = (const float*)d_in[0];
    const void*  ei       = d_in[1];
    const float* num_prop = (const float*)d_in[2];
    const float* num_cat  = (const float*)d_in[3];
    const float* des      = (const float*)d_in[4];
    const float* tw       = (const float*)d_in[5];
    const float* W_des = (const float*)d_in[6];  const float* b_des = (const float*)d_in[7];
    const float* W_tw  = (const float*)d_in[8];  const float* b_tw  = (const float*)d_in[9];
    const float* W_txt = (const float*)d_in[10]; const float* b_txt = (const float*)d_in[11];
    const float* W_np  = (const float*)d_in[12]; const float* b_np  = (const float*)d_in[13];
    const float* W_nc  = (const float*)d_in[14]; const float* b_nc  = (const float*)d_in[15];
    const float* W_in  = (const float*)d_in[16]; const float* b_in  = (const float*)d_in[17];
    const float* W_l   = (const float*)d_in[18]; const float* b_l   = (const float*)d_in[19];
    const float* W_r   = (const float*)d_in[20];
    const float* W_o1  = (const float*)d_in[21]; const float* b_o1  = (const float*)d_in[22];
    const float* W_o2  = (const float*)d_in[23]; const float* b_o2  = (const float*)d_in[24];

    int E = in_sizes[1] / 2;
    if (E > EMAX) E = EMAX;

    float *feat, *h1, *mean, *h2;
    uint32_t* wtf;
    cudaGetSymbolAddress((void**)&feat, g_feat);
    cudaGetSymbolAddress((void**)&h1, g_h1);
    cudaGetSymbolAddress((void**)&mean, g_mean);
    cudaGetSymbolAddress((void**)&h2, g_h2);
    cudaGetSymbolAddress((void**)&wtf, g_wtf);

    float* outp = (float*)d_out;            // [N, 2]
    float* em   = (float*)d_out + 2 * NN;   // [N, 160]

    // weight preconversion offsets: W_des | W_tw | W_txt | W_in | W_l | W_r | W_o1
    WConvArgs wa;
    wa.src[0] = W_des; wa.src[1] = W_tw; wa.src[2] = W_txt;
    wa.src[3] = W_in;  wa.src[4] = W_l;  wa.src[5] = W_r; wa.src[6] = W_o1;
    int sizes[7] = {24576, 24576, 24576, 25600, 25600, 25600, 25600};
    wa.off[0] = 0;
    for (int i = 0; i < 7; i++) wa.off[i + 1] = wa.off[i] + sizes[i];
    const uint32_t* tW_des = wtf + wa.off[0];
    const uint32_t* tW_tw  = wtf + wa.off[1];
    const uint32_t* tW_txt = wtf + wa.off[2];
    const uint32_t* tW_in  = wtf + wa.off[3];
    const uint32_t* tW_l   = wtf + wa.off[4];
    const uint32_t* tW_r   = wtf + wa.off[5];
    const uint32_t* tW_o1  = wtf + wa.off[6];
    wconv_kernel<<<(wa.off[7] + 255) / 256, 256>>>(wa);

    // opt-in to 61,440B dynamic smem for hid_gemm (host-side attr set; capture-safe)
    static bool attr_done = false;
    if (!attr_done) {
        cudaFuncSetAttribute(hid_gemm<false>, cudaFuncAttributeMaxDynamicSharedMemorySize, HIDSMEM);
        cudaFuncSetAttribute(hid_gemm<true>,  cudaFuncAttributeMaxDynamicSharedMemorySize, HIDSMEM);
        attr_done = true;
    }

    dim3 gProj((NN + 127) / 128, 1, 3);
    int gHid = (NN + 63) / 64;
    int gNode8 = (NN + 7) / 8;
    int gEdge = (E + 255) / 256;

    // feature encoder -> g_feat [N,160] (cols: n|c|d|tw|t)
    feat_small_kernel<<<gNode8, 256>>>(num_prop, num_cat, W_np, b_np, W_nc, b_nc, feat);

    ProjArgs pa;
    pa.A[0] = des; pa.W[0] = tW_des; pa.b[0] = b_des; pa.off[0] = 64;
    pa.A[1] = tw;  pa.W[1] = tW_tw;  pa.b[1] = b_tw;  pa.off[1] = 96;
    pa.A[2] = x;   pa.W[2] = tW_txt; pa.b[2] = b_txt; pa.off[2] = 128;
    proj_kernel<<<gProj, 256>>>(pa, feat, NN, 768);

    // h1 = leaky(feat @ W_in + b_in)
    hid_gemm<true><<<gHid, 256, HIDSMEM>>>(feat, tW_in, nullptr, nullptr, b_in, h1, NN, HID, false);

    // CSR build (per-launch, deterministic detection of edge dtype)
    detect_kernel<<<1, 256>>>(ei, E);
    zero_deg_kernel<<<(NN + 255) / 256, 256>>>();
    count_deg_kernel<<<gEdge, 256>>>(ei, E);
    scan_kernel<<<1, 1024>>>();
    fill_csr_kernel<<<gEdge, 256>>>(ei, E);

    // conv1: h2 = mean(h1) @ W_l + b_l + h1 @ W_r
    agg_kernel<<<gNode8, 256>>>(h1, mean);
    hid_gemm<false><<<gHid, 256, HIDSMEM>>>(mean, tW_l, h1, tW_r, b_l, h2, NN, HID, true);

    // conv2: h1 = mean(h2) @ W_l + b_l + h2 @ W_r
    agg_kernel<<<gNode8, 256>>>(h2, mean);
    hid_gemm<false><<<gHid, 256, HIDSMEM>>>(mean, tW_l, h2, tW_r, b_l, h1, NN, HID, true);

    // em = leaky(h1 @ W_o1 + b_o1), written directly into d_out
    hid_gemm<true><<<gHid, 256, HIDSMEM>>>(h1, tW_o1, nullptr, nullptr, b_o1, em, NN, HID, false);

    // out = em @ W_o2 + b_o2
    out2_kernel<<<gNode8, 256>>>(em, W_o2, b_o2, outp);
}

// round 7
// speedup vs baseline: 1.1174x; 1.1174x over previous
#include <cuda_runtime.h>
#include <cstdint>

#define NN 50000
#define EMAX 500000
#define HID 160

// ---------------- scratch (static device globals; no allocation) ----------------
__device__ float g_feat[NN * HID];
__device__ float g_h1[NN * HID];
__device__ float g_mean[NN * HID];
__device__ float g_h2[NN * HID];
__device__ int g_deg[NN];
__device__ int g_offs[NN + 1];
__device__ int g_cursor[NN];
__device__ int g_csr[EMAX];
__device__ int g_is64;
// tf32-preconverted weights: W_des | W_tw | W_txt | W_in | W_l | W_r | W_o1
__device__ uint32_t g_wtf[3 * 24576 + 4 * 25600];

__device__ __forceinline__ float lrelu(float x) { return x > 0.f ? x : 0.01f * x; }

__device__ __forceinline__ uint32_t f2tf32(float x) {
    uint32_t u;
    asm("cvt.rna.tf32.f32 %0, %1;" : "=r"(u) : "f"(x));
    return u;
}

__device__ __forceinline__ void cp16(void* dst_smem, const void* src, bool pred) {
    uint32_t d = (uint32_t)__cvta_generic_to_shared(dst_smem);
    int sz = pred ? 16 : 0;
    asm volatile("cp.async.cg.shared.global [%0], [%1], 16, %2;" :: "r"(d), "l"(src), "r"(sz));
}

// ---------------- weight preconversion (fp32 -> tf32 bits, RNA) ----------------
struct WConvArgs {
    const float* src[7];
    int off[8];
};

__global__ void wconv_kernel(WConvArgs a) {
    int i = blockIdx.x * 256 + threadIdx.x;
    #pragma unroll
    for (int s = 0; s < 7; s++) {
        if (i >= a.off[s] && i < a.off[s + 1])
            g_wtf[i] = f2tf32(a.src[s][i - a.off[s]]);
    }
}

// Edge index may be int64 (reference) or int32 (JAX canonicalization).
__device__ __forceinline__ int edge_val(const void* ei, int idx) {
    if (g_is64) return (int)((const long long*)ei)[idx];
    return ((const int*)ei)[idx];
}

__global__ void detect_kernel(const void* ei, int E) {
    __shared__ int any_hi;
    int t = threadIdx.x;
    if (t == 0) any_hi = 0;
    __syncthreads();
    const unsigned long long* p = (const unsigned long long*)ei;
    int n = E < 1024 ? E : 1024;
    unsigned long long acc = 0;
    for (int i = t; i < n; i += 256) acc |= p[i];
    if (acc > 0xFFFFFFFFull) atomicOr(&any_hi, 1);
    __syncthreads();
    if (t == 0) g_is64 = any_hi ? 0 : 1;
}

// ============ fw_gemm: full-W-resident GEMM, K = N = 160 fixed ============
// C[M,160] = A[M,160] @ W[160,160] (+bias) (optional leaky).
// W (tf32 bits) resident in smem (160 x 168-stride = 107.5KB), loaded once.
// A streamed via 4-stage cp.async ring, one __syncthreads per chunk.
// 512 threads = 16 warps = 4 m-warps x 4 n-warps; warp tile 32m x 40n.
#define FW_S 4
#define FW_WWORDS (160 * 168)
#define FWSMEM (FW_WWORDS * 4 + FW_S * 128 * 36 * 4)

template <bool LEAKY>
__global__ void __launch_bounds__(512, 1) fw_gemm(
    const float* __restrict__ A, const uint32_t* __restrict__ W,
    const float* __restrict__ bias, float* __restrict__ C, int M)
{
    extern __shared__ __align__(16) char smraw[];
    // Ws[k][n] stride 168 (≡8 mod 32): frag bank = (8k+n)%32, conflict-free.
    // As[s][m][k] stride 36: frag bank = (4m+k)%32, conflict-free.
    uint32_t (*Ws)[168] = reinterpret_cast<uint32_t (*)[168]>(smraw);
    float (*As)[128][36] = reinterpret_cast<float (*)[128][36]>(smraw + FW_WWORDS * 4);

    const int t = threadIdx.x;
    const int warp = t >> 5;
    const int lane = t & 31;
    const int mwarp = warp >> 2;        // 0..3
    const int nwarp = warp & 3;         // 0..3
    const int g = lane >> 2;
    const int tg = lane & 3;
    const int blockRow = blockIdx.x * 128;
    const int warpRow = mwarp * 32;
    const int ncol0 = nwarp * 40;

    // A loader: threads 0..255; row t>>1 (0..127), 64B half (t&1)
    const int arow = t >> 1;
    const int acol = (t & 1) * 16;

    auto issueA = [&](int c) {
        if (c <= 4 && t < 256) {
            int buf = c & 3;
            int gr = blockRow + arow;
            const float* src = A + (size_t)gr * HID + c * 32 + acol;
            bool p = gr < M;
            cp16(&As[buf][arow][acol], src, p);
            cp16(&As[buf][arow][acol + 4], src + 4, p);
            cp16(&As[buf][arow][acol + 8], src + 8, p);
            cp16(&As[buf][arow][acol + 12], src + 12, p);
        }
    };

    // prologue: W (once) + A chunks 0..2
    for (int i = t; i < 6400; i += 512) {
        int row = i / 40;
        int c4 = (i % 40) * 4;
        cp16(&Ws[row][c4], W + (size_t)row * HID + c4, true);
    }
    issueA(0);
    asm volatile("cp.async.commit_group;");   // g0 = W + A0
    issueA(1);
    asm volatile("cp.async.commit_group;");   // g1
    issueA(2);
    asm volatile("cp.async.commit_group;");   // g2

    float acc[2][5][4] = {};

    #pragma unroll
    for (int c = 0; c < 5; c++) {
        asm volatile("cp.async.wait_group 2;");   // chunk c (and W) ready
        __syncthreads();
        const int buf = c & 3;
        #pragma unroll
        for (int kk = 0; kk < 32; kk += 8) {
            const int gk = c * 32 + kk;
            uint32_t a[2][4];
            #pragma unroll
            for (int mt = 0; mt < 2; mt++) {
                const int r = warpRow + mt * 16 + g;
                a[mt][0] = f2tf32(As[buf][r][kk + tg]);
                a[mt][1] = f2tf32(As[buf][r + 8][kk + tg]);
                a[mt][2] = f2tf32(As[buf][r][kk + tg + 4]);
                a[mt][3] = f2tf32(As[buf][r + 8][kk + tg + 4]);
            }
            #pragma unroll
            for (int nt = 0; nt < 5; nt++) {
                uint32_t b0 = Ws[gk + tg][ncol0 + nt * 8 + g];
                uint32_t b1 = Ws[gk + tg + 4][ncol0 + nt * 8 + g];
                #pragma unroll
                for (int mt = 0; mt < 2; mt++) {
                    float* cc = acc[mt][nt];
                    asm volatile(
                        "mma.sync.aligned.m16n8k8.row.col.f32.tf32.tf32.f32 "
                        "{%0,%1,%2,%3}, {%4,%5,%6,%7}, {%8,%9}, {%0,%1,%2,%3};"
                        : "+f"(cc[0]), "+f"(cc[1]), "+f"(cc[2]), "+f"(cc[3])
                        : "r"(a[mt][0]), "r"(a[mt][1]), "r"(a[mt][2]), "r"(a[mt][3]),
                          "r"(b0), "r"(b1));
                }
            }
        }
        issueA(c + 3);
        asm volatile("cp.async.commit_group;");   // always commit (may be empty)
    }

    // ---- epilogue ----
    #pragma unroll
    for (int nt = 0; nt < 5; nt++) {
        int lc = ncol0 + nt * 8 + 2 * tg;
        float b0 = bias ? bias[lc] : 0.f;
        float b1 = bias ? bias[lc + 1] : 0.f;
        #pragma unroll
        for (int mt = 0; mt < 2; mt++) {
            float* cc = acc[mt][nt];
            int r0 = blockRow + warpRow + mt * 16 + g;
            int r1 = r0 + 8;
            float v00 = cc[0] + b0, v01 = cc[1] + b1;
            float v10 = cc[2] + b0, v11 = cc[3] + b1;
            if (LEAKY) {
                v00 = lrelu(v00); v01 = lrelu(v01);
                v10 = lrelu(v10); v11 = lrelu(v11);
            }
            if (r0 < M)
                *(float2*)(C + (size_t)r0 * HID + lc) = make_float2(v00, v01);
            if (r1 < M)
                *(float2*)(C + (size_t)r1 * HID + lc) = make_float2(v10, v11);
        }
    }
}

// ============ projection GEMM (768->32, BN=32): round-5 split-K core ============
struct ProjArgs {
    const float* A[3];
    const uint32_t* W[3];
    const float* b[3];
    int off[3];
};

__global__ void __launch_bounds__(256) proj_kernel(ProjArgs pa, float* __restrict__ C,
                                                   int M, int K)
{
    __shared__ __align__(16) float As[2][128][36];
    __shared__ __align__(16) uint32_t Ws[2][32][40];

    const int z = blockIdx.z;
    const float* __restrict__ A = pa.A[z];
    const uint32_t* __restrict__ W = pa.W[z];
    const float* __restrict__ bias = pa.b[z];
    const int cOff = pa.off[z];

    const int t = threadIdx.x;
    const int warp = t >> 5;
    const int lane = t & 31;
    const int mwarp = warp & 3;
    const int kg = warp >> 2;
    const int g = lane >> 2;
    const int tg = lane & 3;
    const int blockRow = blockIdx.x * 128;
    const int warpRow = mwarp * 32;

    const int arow = t >> 1;
    const int acol = (t & 1) * 16;
    const int wrow = t >> 3;
    const int wcol = (t & 7) * 4;

    const int nchunks = K >> 5;

    auto issue = [&](int c) {
        int k0 = c << 5;
        int buf = c & 1;
        int gr = blockRow + arow;
        const float* src = A + (size_t)gr * K + k0 + acol;
        bool p = gr < M;
        #pragma unroll
        for (int j = 0; j < 4; j++)
            cp16(&As[buf][arow][acol + j * 4], src + j * 4, p);
        const uint32_t* wsrc = W + (size_t)(k0 + wrow) * 32 + wcol;
        cp16(&Ws[buf][wrow][wcol], wsrc, true);
        asm volatile("cp.async.commit_group;");
    };

    float acc[2][4][4] = {};

    issue(0);
    for (int c = 0; c < nchunks; c++) {
        if (c + 1 < nchunks) {
            issue(c + 1);
            asm volatile("cp.async.wait_group 1;");
        } else {
            asm volatile("cp.async.wait_group 0;");
        }
        __syncthreads();
        const int buf = c & 1;
        #pragma unroll
        for (int s = 0; s < 2; s++) {
            const int kk = kg * 16 + s * 8;
            uint32_t a[2][4];
            #pragma unroll
            for (int mt = 0; mt < 2; mt++) {
                const int r = warpRow + mt * 16 + g;
                a[mt][0] = f2tf32(As[buf][r][kk + tg]);
                a[mt][1] = f2tf32(As[buf][r + 8][kk + tg]);
                a[mt][2] = f2tf32(As[buf][r][kk + tg + 4]);
                a[mt][3] = f2tf32(As[buf][r + 8][kk + tg + 4]);
            }
            #pragma unroll
            for (int nt = 0; nt < 4; nt++) {
                uint32_t b0 = Ws[buf][kk + tg][nt * 8 + g];
                uint32_t b1 = Ws[buf][kk + tg + 4][nt * 8 + g];
                #pragma unroll
                for (int mt = 0; mt < 2; mt++) {
                    float* cc = acc[mt][nt];
                    asm volatile(
                        "mma.sync.aligned.m16n8k8.row.col.f32.tf32.tf32.f32 "
                        "{%0,%1,%2,%3}, {%4,%5,%6,%7}, {%8,%9}, {%0,%1,%2,%3};"
                        : "+f"(cc[0]), "+f"(cc[1]), "+f"(cc[2]), "+f"(cc[3])
                        : "r"(a[mt][0]), "r"(a[mt][1]), "r"(a[mt][2]), "r"(a[mt][3]),
                          "r"(b0), "r"(b1));
                }
            }
        }
        __syncthreads();
    }

    float* scratch = &As[0][0][0];
    if (kg == 1) {
        #pragma unroll
        for (int mt = 0; mt < 2; mt++)
            #pragma unroll
            for (int nt = 0; nt < 4; nt++)
                #pragma unroll
                for (int i = 0; i < 4; i++) {
                    int combo = (mt * 4 + nt) * 4 + i;
                    scratch[combo * 128 + mwarp * 32 + lane] = acc[mt][nt][i];
                }
    }
    __syncthreads();

    if (kg == 0) {
        #pragma unroll
        for (int nt = 0; nt < 4; nt++) {
            int lc = nt * 8 + 2 * tg;
            float b0 = bias[lc];
            float b1 = bias[lc + 1];
            #pragma unroll
            for (int mt = 0; mt < 2; mt++) {
                float* cc = acc[mt][nt];
                int base = ((mt * 4 + nt) * 4) * 128 + mwarp * 32 + lane;
                float v00 = cc[0] + scratch[base]       + b0;
                float v01 = cc[1] + scratch[base + 128] + b1;
                float v10 = cc[2] + scratch[base + 256] + b0;
                float v11 = cc[3] + scratch[base + 384] + b1;
                v00 = lrelu(v00); v01 = lrelu(v01);
                v10 = lrelu(v10); v11 = lrelu(v11);
                int r0 = blockRow + warpRow + mt * 16 + g;
                int r1 = r0 + 8;
                if (r0 < M)
                    *(float2*)(C + (size_t)r0 * HID + cOff + lc) = make_float2(v00, v01);
                if (r1 < M)
                    *(float2*)(C + (size_t)r1 * HID + cOff + lc) = make_float2(v10, v11);
            }
        }
    }
}

// ---------------- small feature projections: num_prop (6->32), num_category (11->32)
__global__ void __launch_bounds__(256) feat_small_kernel(
    const float* __restrict__ np, const float* __restrict__ nc,
    const float* __restrict__ Wnp, const float* __restrict__ bnp,
    const float* __restrict__ Wnc, const float* __restrict__ bnc,
    float* __restrict__ out)
{
    __shared__ float sWnp[6 * 32];
    __shared__ float sWnc[11 * 32];
    __shared__ float sb[64];
    int t = threadIdx.x;
    for (int i = t; i < 192; i += 256) sWnp[i] = Wnp[i];
    for (int i = t; i < 352; i += 256) sWnc[i] = Wnc[i];
    if (t < 32) sb[t] = bnp[t];
    else if (t < 64) sb[t] = bnc[t - 32];
    __syncthreads();

    int node = blockIdx.x * 8 + (t >> 5);
    int lane = t & 31;
    if (node >= NN) return;

    float a = sb[lane], c = sb[32 + lane];
    #pragma unroll
    for (int k = 0; k < 6; k++) a += np[(size_t)node * 6 + k] * sWnp[k * 32 + lane];
    #pragma unroll
    for (int k = 0; k < 11; k++) c += nc[(size_t)node * 11 + k] * sWnc[k * 32 + lane];
    out[(size_t)node * HID + lane] = lrelu(a);
    out[(size_t)node * HID + 32 + lane] = lrelu(c);
}

// ---------------- CSR build ----------------
__global__ void zero_deg_kernel() {
    int i = blockIdx.x * blockDim.x + threadIdx.x;
    if (i < NN) g_deg[i] = 0;
}

__global__ void count_deg_kernel(const void* __restrict__ ei, int E) {
    int e = blockIdx.x * blockDim.x + threadIdx.x;
    if (e < E) atomicAdd(&g_deg[edge_val(ei, E + e)], 1);
}

__global__ void scan_kernel() {
    __shared__ int part[1024];
    int t = threadIdx.x;
    const int chunk = (NN + 1023) / 1024;
    int s0 = t * chunk;
    int s1 = s0 + chunk; if (s1 > NN) s1 = NN; if (s0 > NN) s0 = NN;
    int s = 0;
    for (int i = s0; i < s1; i++) s += g_deg[i];
    part[t] = s;
    __syncthreads();
    for (int d = 1; d < 1024; d <<= 1) {
        int v = (t >= d) ? part[t - d] : 0;
        __syncthreads();
        part[t] += v;
        __syncthreads();
    }
    int excl = t ? part[t - 1] : 0;
    for (int i = s0; i < s1; i++) {
        g_offs[i] = excl;
        g_cursor[i] = excl;
        excl += g_deg[i];
    }
    if (t == 1023) g_offs[NN] = part[1023];
}

__global__ void fill_csr_kernel(const void* __restrict__ ei, int E) {
    int e = blockIdx.x * blockDim.x + threadIdx.x;
    if (e < E) {
        int d = edge_val(ei, E + e);
        int p = atomicAdd(&g_cursor[d], 1);
        g_csr[p] = edge_val(ei, e);
    }
}

// ---------------- fused mean-aggregate + add: out = mean_nbr(t1) + t2 ----------------
__global__ void __launch_bounds__(256) agg_add_kernel(
    const float* __restrict__ t1, const float* __restrict__ t2,
    float* __restrict__ out)
{
    int w = (blockIdx.x * blockDim.x + threadIdx.x) >> 5;
    int lane = threadIdx.x & 31;
    if (w >= NN) return;
    int beg = g_offs[w], end = g_offs[w + 1];
    float a0 = 0.f, a1 = 0.f, a2 = 0.f, a3 = 0.f, a4 = 0.f;
    int e = beg;
    for (; e + 2 <= end; e += 2) {
        const float* ra = t1 + (size_t)g_csr[e] * HID;
        const float* rb = t1 + (size_t)g_csr[e + 1] * HID;
        float x0 = ra[lane],       y0 = rb[lane];
        float x1 = ra[lane + 32],  y1 = rb[lane + 32];
        float x2 = ra[lane + 64],  y2 = rb[lane + 64];
        float x3 = ra[lane + 96],  y3 = rb[lane + 96];
        float x4 = ra[lane + 128], y4 = rb[lane + 128];
        a0 += x0 + y0; a1 += x1 + y1; a2 += x2 + y2;
        a3 += x3 + y3; a4 += x4 + y4;
    }
    if (e < end) {
        const float* ra = t1 + (size_t)g_csr[e] * HID;
        a0 += ra[lane];       a1 += ra[lane + 32];  a2 += ra[lane + 64];
        a3 += ra[lane + 96];  a4 += ra[lane + 128];
    }
    int deg = end - beg;
    float inv = 1.f / (float)(deg > 0 ? deg : 1);
    const float* b = t2 + (size_t)w * HID;
    float* m = out + (size_t)w * HID;
    m[lane]       = a0 * inv + b[lane];
    m[lane + 32]  = a1 * inv + b[lane + 32];
    m[lane + 64]  = a2 * inv + b[lane + 64];
    m[lane + 96]  = a3 * inv + b[lane + 96];
    m[lane + 128] = a4 * inv + b[lane + 128];
}

// ---------------- final 160->2 head: one warp per node ----------------
__global__ void __launch_bounds__(256) out2_kernel(
    const float* __restrict__ em, const float* __restrict__ W,
    const float* __restrict__ b, float* __restrict__ out)
{
    __shared__ float sW[320];
    int t = threadIdx.x;
    for (int i = t; i < 320; i += 256) sW[i] = W[i];
    __syncthreads();
    int node = blockIdx.x * 8 + (t >> 5);
    int lane = t & 31;
    if (node >= NN) return;
    float a0 = 0.f, a1 = 0.f;
    #pragma unroll
    for (int c = 0; c < 5; c++) {
        int k = lane + 32 * c;
        float v = em[(size_t)node * HID + k];
        a0 += v * sW[k * 2];
        a1 += v * sW[k * 2 + 1];
    }
    #pragma unroll
    for (int o = 16; o > 0; o >>= 1) {
        a0 += __shfl_down_sync(0xffffffffu, a0, o);
        a1 += __shfl_down_sync(0xffffffffu, a1, o);
    }
    if (lane == 0) {
        out[(size_t)node * 2]     = a0 + b[0];
        out[(size_t)node * 2 + 1] = a1 + b[1];
    }
}

// ---------------- launch ----------------
extern "C" void kernel_launch(void* const* d_in, const int* in_sizes, int n_in,
                              void* d_out, int out_size)
{
    const float* x        = (const float*)d_in[0];
    const void*  ei       = d_in[1];
    const float* num_prop = (const float*)d_in[2];
    const float* num_cat  = (const float*)d_in[3];
    const float* des      = (const float*)d_in[4];
    const float* tw       = (const float*)d_in[5];
    const float* W_des = (const float*)d_in[6];  const float* b_des = (const float*)d_in[7];
    const float* W_tw  = (const float*)d_in[8];  const float* b_tw  = (const float*)d_in[9];
    const float* W_txt = (const float*)d_in[10]; const float* b_txt = (const float*)d_in[11];
    const float* W_np  = (const float*)d_in[12]; const float* b_np  = (const float*)d_in[13];
    const float* W_nc  = (const float*)d_in[14]; const float* b_nc  = (const float*)d_in[15];
    const float* W_in  = (const float*)d_in[16]; const float* b_in  = (const float*)d_in[17];
    const float* W_l   = (const float*)d_in[18]; const float* b_l   = (const float*)d_in[19];
    const float* W_r   = (const float*)d_in[20];
    const float* W_o1  = (const float*)d_in[21]; const float* b_o1  = (const float*)d_in[22];
    const float* W_o2  = (const float*)d_in[23]; const float* b_o2  = (const float*)d_in[24];

    int E = in_sizes[1] / 2;
    if (E > EMAX) E = EMAX;

    float *feat, *h1, *mean, *h2;
    uint32_t* wtf;
    cudaGetSymbolAddress((void**)&feat, g_feat);
    cudaGetSymbolAddress((void**)&h1, g_h1);
    cudaGetSymbolAddress((void**)&mean, g_mean);
    cudaGetSymbolAddress((void**)&h2, g_h2);
    cudaGetSymbolAddress((void**)&wtf, g_wtf);

    float* outp = (float*)d_out;            // [N, 2]
    float* em   = (float*)d_out + 2 * NN;   // [N, 160]

    // weight preconversion offsets: W_des | W_tw | W_txt | W_in | W_l | W_r | W_o1
    WConvArgs wa;
    wa.src[0] = W_des; wa.src[1] = W_tw; wa.src[2] = W_txt;
    wa.src[3] = W_in;  wa.src[4] = W_l;  wa.src[5] = W_r; wa.src[6] = W_o1;
    int sizes[7] = {24576, 24576, 24576, 25600, 25600, 25600, 25600};
    wa.off[0] = 0;
    for (int i = 0; i < 7; i++) wa.off[i + 1] = wa.off[i] + sizes[i];
    const uint32_t* tW_des = wtf + wa.off[0];
    const uint32_t* tW_tw  = wtf + wa.off[1];
    const uint32_t* tW_txt = wtf + wa.off[2];
    const uint32_t* tW_in  = wtf + wa.off[3];
    const uint32_t* tW_l   = wtf + wa.off[4];
    const uint32_t* tW_r   = wtf + wa.off[5];
    const uint32_t* tW_o1  = wtf + wa.off[6];
    wconv_kernel<<<(wa.off[7] + 255) / 256, 256>>>(wa);

    static bool attr_done = false;
    if (!attr_done) {
        cudaFuncSetAttribute(fw_gemm<false>, cudaFuncAttributeMaxDynamicSharedMemorySize, FWSMEM);
        cudaFuncSetAttribute(fw_gemm<true>,  cudaFuncAttributeMaxDynamicSharedMemorySize, FWSMEM);
        attr_done = true;
    }

    dim3 gProj((NN + 127) / 128, 1, 3);
    int gFw = (NN + 127) / 128;
    int gNode8 = (NN + 7) / 8;
    int gEdge = (E + 255) / 256;

    // feature encoder -> g_feat [N,160] (cols: n|c|d|tw|t)
    feat_small_kernel<<<gNode8, 256>>>(num_prop, num_cat, W_np, b_np, W_nc, b_nc, feat);
    ProjArgs pa;
    pa.A[0] = des; pa.W[0] = tW_des; pa.b[0] = b_des; pa.off[0] = 64;
    pa.A[1] = tw;  pa.W[1] = tW_tw;  pa.b[1] = b_tw;  pa.off[1] = 96;
    pa.A[2] = x;   pa.W[2] = tW_txt; pa.b[2] = b_txt; pa.off[2] = 128;
    proj_kernel<<<gProj, 256>>>(pa, feat, NN, 768);

    // h1 = leaky(feat @ W_in + b_in)
    fw_gemm<true><<<gFw, 512, FWSMEM>>>(feat, tW_in, b_in, h1, NN);

    // CSR build (per-launch, deterministic edge-dtype detection)
    detect_kernel<<<1, 256>>>(ei, E);
    zero_deg_kernel<<<(NN + 255) / 256, 256>>>();
    count_deg_kernel<<<gEdge, 256>>>(ei, E);
    scan_kernel<<<1, 1024>>>();
    fill_csr_kernel<<<gEdge, 256>>>(ei, E);

    // conv1: h2 = mean_nbr(h1 @ W_l) + (h1 @ W_r + b_l)   [mean/matmul commute: linearity]
    fw_gemm<false><<<gFw, 512, FWSMEM>>>(h1, tW_l, nullptr, mean, NN);   // t1
    fw_gemm<false><<<gFw, 512, FWSMEM>>>(h1, tW_r, b_l, feat, NN);       // t2 (feat is dead)
    agg_add_kernel<<<gNode8, 256>>>(mean, feat, h2);

    // conv2: h1 = mean_nbr(h2 @ W_l) + (h2 @ W_r + b_l)
    fw_gemm<false><<<gFw, 512, FWSMEM>>>(h2, tW_l, nullptr, mean, NN);
    fw_gemm<false><<<gFw, 512, FWSMEM>>>(h2, tW_r, b_l, feat, NN);
    agg_add_kernel<<<gNode8, 256>>>(mean, feat, h1);

    // em = leaky(h1 @ W_o1 + b_o1), written directly into d_out
    fw_gemm<true><<<gFw, 512, FWSMEM>>>(h1, tW_o1, b_o1, em, NN);

    // out = em @ W_o2 + b_o2
    out2_kernel<<<gNode8, 256>>>(em, W_o2, b_o2, outp);
}

// round 8
// speedup vs baseline: 1.1878x; 1.0630x over previous
#include <cuda_runtime.h>
#include <cstdint>

#define NN 50000
#define EMAX 500000
#define HID 160

// ---------------- scratch (static device globals; no allocation) ----------------
__device__ float g_feat[NN * HID];
__device__ float g_h1[NN * HID];
__device__ float g_mean[NN * HID];
__device__ float g_h2[NN * HID];
__device__ int g_deg[NN];
__device__ int g_offs[NN + 1];
__device__ int g_cursor[NN];
__device__ int g_csr[EMAX];
__device__ int g_is64;
// tf32-preconverted weights: W_des | W_tw | W_txt | W_in | W_l | W_r | W_o1
__device__ uint32_t g_wtf[3 * 24576 + 4 * 25600];

__device__ __forceinline__ float lrelu(float x) { return x > 0.f ? x : 0.01f * x; }

__device__ __forceinline__ uint32_t f2tf32(float x) {
    uint32_t u;
    asm("cvt.rna.tf32.f32 %0, %1;" : "=r"(u) : "f"(x));
    return u;
}

__device__ __forceinline__ void cp16(void* dst_smem, const void* src, bool pred) {
    uint32_t d = (uint32_t)__cvta_generic_to_shared(dst_smem);
    int sz = pred ? 16 : 0;
    asm volatile("cp.async.cg.shared.global [%0], [%1], 16, %2;" :: "r"(d), "l"(src), "r"(sz));
}

// ---------------- weight preconversion (fp32 -> tf32 bits, RNA) ----------------
struct WConvArgs {
    const float* src[7];
    int off[8];
};

__global__ void wconv_kernel(WConvArgs a) {
    int i = blockIdx.x * 256 + threadIdx.x;
    #pragma unroll
    for (int s = 0; s < 7; s++) {
        if (i >= a.off[s] && i < a.off[s + 1])
            g_wtf[i] = f2tf32(a.src[s][i - a.off[s]]);
    }
}

// Edge index may be int64 (reference) or int32 (JAX canonicalization).
__device__ __forceinline__ int edge_val(const void* ei, int idx) {
    if (g_is64) return (int)((const long long*)ei)[idx];
    return ((const int*)ei)[idx];
}

__global__ void detect_kernel(const void* ei, int E) {
    __shared__ int any_hi;
    int t = threadIdx.x;
    if (t == 0) any_hi = 0;
    __syncthreads();
    const unsigned long long* p = (const unsigned long long*)ei;
    int n = E < 1024 ? E : 1024;
    unsigned long long acc = 0;
    for (int i = t; i < n; i += 256) acc |= p[i];
    if (acc > 0xFFFFFFFFull) atomicOr(&any_hi, 1);
    __syncthreads();
    if (t == 0) g_is64 = any_hi ? 0 : 1;
}

// ============ fw_gemm_p: persistent full-W-resident GEMM, K=N=160 ============
// C[M,160] = leaky?(A[M,160] @ W + bias). W in smem once per BLOCK (persistent).
// grid=148; each block loops row tiles of 128. 512 thr = 4m x 4n warps, 32x40 tile.
#define FW_WWORDS (160 * 168)
#define FWSMEM (FW_WWORDS * 4 + 4 * 128 * 36 * 4)   // 107520 + 73728 = 181248

template <bool LEAKY>
__global__ void __launch_bounds__(512, 1) fw_gemm_p(
    const float* __restrict__ A, const uint32_t* __restrict__ W,
    const float* __restrict__ bias, float* __restrict__ C, int M)
{
    extern __shared__ __align__(16) char smraw[];
    uint32_t (*Ws)[168] = reinterpret_cast<uint32_t (*)[168]>(smraw);
    float (*As)[128][36] = reinterpret_cast<float (*)[128][36]>(smraw + FW_WWORDS * 4);

    const int t = threadIdx.x;
    const int warp = t >> 5, lane = t & 31;
    const int mwarp = warp >> 2, nwarp = warp & 3;
    const int g = lane >> 2, tg = lane & 3;
    const int warpRow = mwarp * 32, ncol0 = nwarp * 40;
    const int arow = t >> 1, acol = (t & 1) * 16;

    // W resident (once per block)
    for (int i = t; i < 6400; i += 512) {
        int row = i / 40, c4 = (i % 40) * 4;
        cp16(&Ws[row][c4], W + (size_t)row * HID + c4, true);
    }

    const int ntiles = (M + 127) >> 7;
    for (int tile = blockIdx.x; tile < ntiles; tile += gridDim.x) {
        const int blockRow = tile << 7;
        auto issueA = [&](int c) {
            if (c <= 4 && t < 256) {
                int buf = c & 3;
                int gr = blockRow + arow;
                const float* src = A + (size_t)gr * HID + c * 32 + acol;
                bool p = gr < M;
                cp16(&As[buf][arow][acol], src, p);
                cp16(&As[buf][arow][acol + 4], src + 4, p);
                cp16(&As[buf][arow][acol + 8], src + 8, p);
                cp16(&As[buf][arow][acol + 12], src + 12, p);
            }
        };
        issueA(0); asm volatile("cp.async.commit_group;");
        issueA(1); asm volatile("cp.async.commit_group;");
        issueA(2); asm volatile("cp.async.commit_group;");

        float acc[2][5][4] = {};
        #pragma unroll
        for (int c = 0; c < 5; c++) {
            asm volatile("cp.async.wait_group 2;");
            __syncthreads();
            const int buf = c & 3;
            #pragma unroll
            for (int kk = 0; kk < 32; kk += 8) {
                const int gk = c * 32 + kk;
                uint32_t a[2][4];
                #pragma unroll
                for (int mt = 0; mt < 2; mt++) {
                    const int r = warpRow + mt * 16 + g;
                    a[mt][0] = f2tf32(As[buf][r][kk + tg]);
                    a[mt][1] = f2tf32(As[buf][r + 8][kk + tg]);
                    a[mt][2] = f2tf32(As[buf][r][kk + tg + 4]);
                    a[mt][3] = f2tf32(As[buf][r + 8][kk + tg + 4]);
                }
                #pragma unroll
                for (int nt = 0; nt < 5; nt++) {
                    uint32_t b0 = Ws[gk + tg][ncol0 + nt * 8 + g];
                    uint32_t b1 = Ws[gk + tg + 4][ncol0 + nt * 8 + g];
                    #pragma unroll
                    for (int mt = 0; mt < 2; mt++) {
                        float* cc = acc[mt][nt];
                        asm volatile(
                            "mma.sync.aligned.m16n8k8.row.col.f32.tf32.tf32.f32 "
                            "{%0,%1,%2,%3}, {%4,%5,%6,%7}, {%8,%9}, {%0,%1,%2,%3};"
                            : "+f"(cc[0]), "+f"(cc[1]), "+f"(cc[2]), "+f"(cc[3])
                            : "r"(a[mt][0]), "r"(a[mt][1]), "r"(a[mt][2]), "r"(a[mt][3]),
                              "r"(b0), "r"(b1));
                    }
                }
            }
            issueA(c + 3);
            asm volatile("cp.async.commit_group;");
        }

        #pragma unroll
        for (int nt = 0; nt < 5; nt++) {
            int lc = ncol0 + nt * 8 + 2 * tg;
            float b0 = bias[lc];
            float b1 = bias[lc + 1];
            #pragma unroll
            for (int mt = 0; mt < 2; mt++) {
                float* cc = acc[mt][nt];
                int r0 = blockRow + warpRow + mt * 16 + g;
                int r1 = r0 + 8;
                float v00 = cc[0] + b0, v01 = cc[1] + b1;
                float v10 = cc[2] + b0, v11 = cc[3] + b1;
                if (LEAKY) {
                    v00 = lrelu(v00); v01 = lrelu(v01);
                    v10 = lrelu(v10); v11 = lrelu(v11);
                }
                if (r0 < M)
                    *(float2*)(C + (size_t)r0 * HID + lc) = make_float2(v00, v01);
                if (r1 < M)
                    *(float2*)(C + (size_t)r1 * HID + lc) = make_float2(v10, v11);
            }
        }
        __syncthreads();   // protect A-ring reuse across tiles
    }
}

// ============ fw_dual: persistent dual-W GEMM for SAGE conv ============
// C1 = A @ W_l ; C2 = A @ W_r + bias.  Both W resident: Ws[160][328]
// (cols 0..159 = W_l, 160..319 = W_r). BM=64, 2-stage A ring.
// 512 thr = 2 m-warps x 8 n-warps; warp tile 32m x 40n.
#define FD_STRIDE 328
#define FD_WWORDS (160 * FD_STRIDE)
#define FDSMEM (FD_WWORDS * 4 + 2 * 64 * 36 * 4)     // 209920 + 18432 = 228352

__global__ void __launch_bounds__(512, 1) fw_dual(
    const float* __restrict__ A, const uint32_t* __restrict__ Wl,
    const uint32_t* __restrict__ Wr, const float* __restrict__ bias,
    float* __restrict__ C1, float* __restrict__ C2, int M)
{
    extern __shared__ __align__(16) char smraw[];
    uint32_t (*Ws)[FD_STRIDE] = reinterpret_cast<uint32_t (*)[FD_STRIDE]>(smraw);
    float (*As)[64][36] = reinterpret_cast<float (*)[64][36]>(smraw + FD_WWORDS * 4);

    const int t = threadIdx.x;
    const int warp = t >> 5, lane = t & 31;
    const int mwarp = warp >> 3, nwarp = warp & 7;
    const int g = lane >> 2, tg = lane & 3;
    const int warpRow = mwarp * 32, ncol0 = nwarp * 40;
    const int arow = t >> 3, acol = (t & 7) * 4;

    // both W matrices resident (once per block)
    for (int i = t; i < 12800; i += 512) {
        int row = i / 80, c4 = (i % 80) * 4;
        const uint32_t* src = (c4 < 160) ? (Wl + (size_t)row * HID + c4)
                                         : (Wr + (size_t)row * HID + (c4 - 160));
        cp16(&Ws[row][c4], src, true);
    }

    const int ntiles = (M + 63) >> 6;
    for (int tile = blockIdx.x; tile < ntiles; tile += gridDim.x) {
        const int blockRow = tile << 6;
        auto issueA = [&](int c) {
            if (c <= 4) {
                int buf = c & 1;
                int gr = blockRow + arow;
                const float* src = A + (size_t)gr * HID + c * 32 + acol;
                cp16(&As[buf][arow][acol], src, gr < M);
            }
        };
        issueA(0); asm volatile("cp.async.commit_group;");
        issueA(1); asm volatile("cp.async.commit_group;");

        float acc[2][5][4] = {};
        #pragma unroll
        for (int c = 0; c < 5; c++) {
            asm volatile("cp.async.wait_group 1;");
            __syncthreads();
            const int buf = c & 1;
            #pragma unroll
            for (int kk = 0; kk < 32; kk += 8) {
                const int gk = c * 32 + kk;
                uint32_t a[2][4];
                #pragma unroll
                for (int mt = 0; mt < 2; mt++) {
                    const int r = warpRow + mt * 16 + g;
                    a[mt][0] = f2tf32(As[buf][r][kk + tg]);
                    a[mt][1] = f2tf32(As[buf][r + 8][kk + tg]);
                    a[mt][2] = f2tf32(As[buf][r][kk + tg + 4]);
                    a[mt][3] = f2tf32(As[buf][r + 8][kk + tg + 4]);
                }
                #pragma unroll
                for (int nt = 0; nt < 5; nt++) {
                    uint32_t b0 = Ws[gk + tg][ncol0 + nt * 8 + g];
                    uint32_t b1 = Ws[gk + tg + 4][ncol0 + nt * 8 + g];
                    #pragma unroll
                    for (int mt = 0; mt < 2; mt++) {
                        float* cc = acc[mt][nt];
                        asm volatile(
                            "mma.sync.aligned.m16n8k8.row.col.f32.tf32.tf32.f32 "
                            "{%0,%1,%2,%3}, {%4,%5,%6,%7}, {%8,%9}, {%0,%1,%2,%3};"
                            : "+f"(cc[0]), "+f"(cc[1]), "+f"(cc[2]), "+f"(cc[3])
                            : "r"(a[mt][0]), "r"(a[mt][1]), "r"(a[mt][2]), "r"(a[mt][3]),
                              "r"(b0), "r"(b1));
                    }
                }
            }
            __syncthreads();   // 2-stage ring: all reads of buf done before re-issue
            issueA(c + 2);
            asm volatile("cp.async.commit_group;");
        }

        // epilogue: n-warps 0..3 -> C1 (no bias); 4..7 -> C2 (+bias)
        float* Cout = (nwarp < 4) ? C1 : C2;
        const int cb = (nwarp < 4) ? ncol0 : (ncol0 - 160);
        const bool useb = (nwarp >= 4);
        #pragma unroll
        for (int nt = 0; nt < 5; nt++) {
            int lc = cb + nt * 8 + 2 * tg;
            float b0 = useb ? bias[lc] : 0.f;
            float b1 = useb ? bias[lc + 1] : 0.f;
            #pragma unroll
            for (int mt = 0; mt < 2; mt++) {
                float* cc = acc[mt][nt];
                int r0 = blockRow + warpRow + mt * 16 + g;
                int r1 = r0 + 8;
                if (r0 < M)
                    *(float2*)(Cout + (size_t)r0 * HID + lc) = make_float2(cc[0] + b0, cc[1] + b1);
                if (r1 < M)
                    *(float2*)(Cout + (size_t)r1 * HID + lc) = make_float2(cc[2] + b0, cc[3] + b1);
            }
        }
        __syncthreads();   // protect A-ring reuse across tiles
    }
}

// ============ projection GEMM (768->32, BN=32): split-K core ============
struct ProjArgs {
    const float* A[3];
    const uint32_t* W[3];
    const float* b[3];
    int off[3];
};

__global__ void __launch_bounds__(256) proj_kernel(ProjArgs pa, float* __restrict__ C,
                                                   int M, int K)
{
    __shared__ __align__(16) float As[2][128][36];
    __shared__ __align__(16) uint32_t Ws[2][32][40];

    const int z = blockIdx.z;
    const float* __restrict__ A = pa.A[z];
    const uint32_t* __restrict__ W = pa.W[z];
    const float* __restrict__ bias = pa.b[z];
    const int cOff = pa.off[z];

    const int t = threadIdx.x;
    const int warp = t >> 5;
    const int lane = t & 31;
    const int mwarp = warp & 3;
    const int kg = warp >> 2;
    const int g = lane >> 2;
    const int tg = lane & 3;
    const int blockRow = blockIdx.x * 128;
    const int warpRow = mwarp * 32;

    const int arow = t >> 1;
    const int acol = (t & 1) * 16;
    const int wrow = t >> 3;
    const int wcol = (t & 7) * 4;

    const int nchunks = K >> 5;

    auto issue = [&](int c) {
        int k0 = c << 5;
        int buf = c & 1;
        int gr = blockRow + arow;
        const float* src = A + (size_t)gr * K + k0 + acol;
        bool p = gr < M;
        #pragma unroll
        for (int j = 0; j < 4; j++)
            cp16(&As[buf][arow][acol + j * 4], src + j * 4, p);
        const uint32_t* wsrc = W + (size_t)(k0 + wrow) * 32 + wcol;
        cp16(&Ws[buf][wrow][wcol], wsrc, true);
        asm volatile("cp.async.commit_group;");
    };

    float acc[2][4][4] = {};

    issue(0);
    for (int c = 0; c < nchunks; c++) {
        if (c + 1 < nchunks) {
            issue(c + 1);
            asm volatile("cp.async.wait_group 1;");
        } else {
            asm volatile("cp.async.wait_group 0;");
        }
        __syncthreads();
        const int buf = c & 1;
        #pragma unroll
        for (int s = 0; s < 2; s++) {
            const int kk = kg * 16 + s * 8;
            uint32_t a[2][4];
            #pragma unroll
            for (int mt = 0; mt < 2; mt++) {
                const int r = warpRow + mt * 16 + g;
                a[mt][0] = f2tf32(As[buf][r][kk + tg]);
                a[mt][1] = f2tf32(As[buf][r + 8][kk + tg]);
                a[mt][2] = f2tf32(As[buf][r][kk + tg + 4]);
                a[mt][3] = f2tf32(As[buf][r + 8][kk + tg + 4]);
            }
            #pragma unroll
            for (int nt = 0; nt < 4; nt++) {
                uint32_t b0 = Ws[buf][kk + tg][nt * 8 + g];
                uint32_t b1 = Ws[buf][kk + tg + 4][nt * 8 + g];
                #pragma unroll
                for (int mt = 0; mt < 2; mt++) {
                    float* cc = acc[mt][nt];
                    asm volatile(
                        "mma.sync.aligned.m16n8k8.row.col.f32.tf32.tf32.f32 "
                        "{%0,%1,%2,%3}, {%4,%5,%6,%7}, {%8,%9}, {%0,%1,%2,%3};"
                        : "+f"(cc[0]), "+f"(cc[1]), "+f"(cc[2]), "+f"(cc[3])
                        : "r"(a[mt][0]), "r"(a[mt][1]), "r"(a[mt][2]), "r"(a[mt][3]),
                          "r"(b0), "r"(b1));
                }
            }
        }
        __syncthreads();
    }

    float* scratch = &As[0][0][0];
    if (kg == 1) {
        #pragma unroll
        for (int mt = 0; mt < 2; mt++)
            #pragma unroll
            for (int nt = 0; nt < 4; nt++)
                #pragma unroll
                for (int i = 0; i < 4; i++) {
                    int combo = (mt * 4 + nt) * 4 + i;
                    scratch[combo * 128 + mwarp * 32 + lane] = acc[mt][nt][i];
                }
    }
    __syncthreads();

    if (kg == 0) {
        #pragma unroll
        for (int nt = 0; nt < 4; nt++) {
            int lc = nt * 8 + 2 * tg;
            float b0 = bias[lc];
            float b1 = bias[lc + 1];
            #pragma unroll
            for (int mt = 0; mt < 2; mt++) {
                float* cc = acc[mt][nt];
                int base = ((mt * 4 + nt) * 4) * 128 + mwarp * 32 + lane;
                float v00 = cc[0] + scratch[base]       + b0;
                float v01 = cc[1] + scratch[base + 128] + b1;
                float v10 = cc[2] + scratch[base + 256] + b0;
                float v11 = cc[3] + scratch[base + 384] + b1;
                v00 = lrelu(v00); v01 = lrelu(v01);
                v10 = lrelu(v10); v11 = lrelu(v11);
                int r0 = blockRow + warpRow + mt * 16 + g;
                int r1 = r0 + 8;
                if (r0 < M)
                    *(float2*)(C + (size_t)r0 * HID + cOff + lc) = make_float2(v00, v01);
                if (r1 < M)
                    *(float2*)(C + (size_t)r1 * HID + cOff + lc) = make_float2(v10, v11);
            }
        }
    }
}

// ---------------- small feature projections: num_prop (6->32), num_category (11->32)
__global__ void __launch_bounds__(256) feat_small_kernel(
    const float* __restrict__ np, const float* __restrict__ nc,
    const float* __restrict__ Wnp, const float* __restrict__ bnp,
    const float* __restrict__ Wnc, const float* __restrict__ bnc,
    float* __restrict__ out)
{
    __shared__ float sWnp[6 * 32];
    __shared__ float sWnc[11 * 32];
    __shared__ float sb[64];
    int t = threadIdx.x;
    for (int i = t; i < 192; i += 256) sWnp[i] = Wnp[i];
    for (int i = t; i < 352; i += 256) sWnc[i] = Wnc[i];
    if (t < 32) sb[t] = bnp[t];
    else if (t < 64) sb[t] = bnc[t - 32];
    __syncthreads();

    int node = blockIdx.x * 8 + (t >> 5);
    int lane = t & 31;
    if (node >= NN) return;

    float a = sb[lane], c = sb[32 + lane];
    #pragma unroll
    for (int k = 0; k < 6; k++) a += np[(size_t)node * 6 + k] * sWnp[k * 32 + lane];
    #pragma unroll
    for (int k = 0; k < 11; k++) c += nc[(size_t)node * 11 + k] * sWnc[k * 32 + lane];
    out[(size_t)node * HID + lane] = lrelu(a);
    out[(size_t)node * HID + 32 + lane] = lrelu(c);
}

// ---------------- CSR build ----------------
__global__ void zero_deg_kernel() {
    int i = blockIdx.x * blockDim.x + threadIdx.x;
    if (i < NN) g_deg[i] = 0;
}

__global__ void count_deg_kernel(const void* __restrict__ ei, int E) {
    int e = blockIdx.x * blockDim.x + threadIdx.x;
    if (e < E) atomicAdd(&g_deg[edge_val(ei, E + e)], 1);
}

__global__ void scan_kernel() {
    __shared__ int part[1024];
    int t = threadIdx.x;
    const int chunk = (NN + 1023) / 1024;
    int s0 = t * chunk;
    int s1 = s0 + chunk; if (s1 > NN) s1 = NN; if (s0 > NN) s0 = NN;
    int s = 0;
    for (int i = s0; i < s1; i++) s += g_deg[i];
    part[t] = s;
    __syncthreads();
    for (int d = 1; d < 1024; d <<= 1) {
        int v = (t >= d) ? part[t - d] : 0;
        __syncthreads();
        part[t] += v;
        __syncthreads();
    }
    int excl = t ? part[t - 1] : 0;
    for (int i = s0; i < s1; i++) {
        g_offs[i] = excl;
        g_cursor[i] = excl;
        excl += g_deg[i];
    }
    if (t == 1023) g_offs[NN] = part[1023];
}

__global__ void fill_csr_kernel(const void* __restrict__ ei, int E) {
    int e = blockIdx.x * blockDim.x + threadIdx.x;
    if (e < E) {
        int d = edge_val(ei, E + e);
        int p = atomicAdd(&g_cursor[d], 1);
        g_csr[p] = edge_val(ei, e);
    }
}

// ---------------- fused mean-aggregate + add: out = mean_nbr(t1) + t2 ----------------
__global__ void __launch_bounds__(256) agg_add_kernel(
    const float* __restrict__ t1, const float* __restrict__ t2,
    float* __restrict__ out)
{
    int w = (blockIdx.x * blockDim.x + threadIdx.x) >> 5;
    int lane = threadIdx.x & 31;
    if (w >= NN) return;
    int beg = g_offs[w], end = g_offs[w + 1];
    float a0 = 0.f, a1 = 0.f, a2 = 0.f, a3 = 0.f, a4 = 0.f;
    int e = beg;
    for (; e + 2 <= end; e += 2) {
        const float* ra = t1 + (size_t)g_csr[e] * HID;
        const float* rb = t1 + (size_t)g_csr[e + 1] * HID;
        float x0 = ra[lane],       y0 = rb[lane];
        float x1 = ra[lane + 32],  y1 = rb[lane + 32];
        float x2 = ra[lane + 64],  y2 = rb[lane + 64];
        float x3 = ra[lane + 96],  y3 = rb[lane + 96];
        float x4 = ra[lane + 128], y4 = rb[lane + 128];
        a0 += x0 + y0; a1 += x1 + y1; a2 += x2 + y2;
        a3 += x3 + y3; a4 += x4 + y4;
    }
    if (e < end) {
        const float* ra = t1 + (size_t)g_csr[e] * HID;
        a0 += ra[lane];       a1 += ra[lane + 32];  a2 += ra[lane + 64];
        a3 += ra[lane + 96];  a4 += ra[lane + 128];
    }
    int deg = end - beg;
    float inv = 1.f / (float)(deg > 0 ? deg : 1);
    const float* b = t2 + (size_t)w * HID;
    float* m = out + (size_t)w * HID;
    m[lane]       = a0 * inv + b[lane];
    m[lane + 32]  = a1 * inv + b[lane + 32];
    m[lane + 64]  = a2 * inv + b[lane + 64];
    m[lane + 96]  = a3 * inv + b[lane + 96];
    m[lane + 128] = a4 * inv + b[lane + 128];
}

// ---------------- final 160->2 head: one warp per node ----------------
__global__ void __launch_bounds__(256) out2_kernel(
    const float* __restrict__ em, const float* __restrict__ W,
    const float* __restrict__ b, float* __restrict__ out)
{
    __shared__ float sW[320];
    int t = threadIdx.x;
    for (int i = t; i < 320; i += 256) sW[i] = W[i];
    __syncthreads();
    int node = blockIdx.x * 8 + (t >> 5);
    int lane = t & 31;
    if (node >= NN) return;
    float a0 = 0.f, a1 = 0.f;
    #pragma unroll
    for (int c = 0; c < 5; c++) {
        int k = lane + 32 * c;
        float v = em[(size_t)node * HID + k];
        a0 += v * sW[k * 2];
        a1 += v * sW[k * 2 + 1];
    }
    #pragma unroll
    for (int o = 16; o > 0; o >>= 1) {
        a0 += __shfl_down_sync(0xffffffffu, a0, o);
        a1 += __shfl_down_sync(0xffffffffu, a1, o);
    }
    if (lane == 0) {
        out[(size_t)node * 2]     = a0 + b[0];
        out[(size_t)node * 2 + 1] = a1 + b[1];
    }
}

// ---------------- launch ----------------
extern "C" void kernel_launch(void* const* d_in, const int* in_sizes, int n_in,
                              void* d_out, int out_size)
{
    const float* x        = (const float*)d_in[0];
    const void*  ei       = d_in[1];
    const float* num_prop = (const float*)d_in[2];
    const float* num_cat  = (const float*)d_in[3];
    const float* des      = (const float*)d_in[4];
    const float* tw       = (const float*)d_in[5];
    const float* W_des = (const float*)d_in[6];  const float* b_des = (const float*)d_in[7];
    const float* W_tw  = (const float*)d_in[8];  const float* b_tw  = (const float*)d_in[9];
    const float* W_txt = (const float*)d_in[10]; const float* b_txt = (const float*)d_in[11];
    const float* W_np  = (const float*)d_in[12]; const float* b_np  = (const float*)d_in[13];
    const float* W_nc  = (const float*)d_in[14]; const float* b_nc  = (const float*)d_in[15];
    const float* W_in  = (const float*)d_in[16]; const float* b_in  = (const float*)d_in[17];
    const float* W_l   = (const float*)d_in[18]; const float* b_l   = (const float*)d_in[19];
    const float* W_r   = (const float*)d_in[20];
    const float* W_o1  = (const float*)d_in[21]; const float* b_o1  = (const float*)d_in[22];
    const float* W_o2  = (const float*)d_in[23]; const float* b_o2  = (const float*)d_in[24];

    int E = in_sizes[1] / 2;
    if (E > EMAX) E = EMAX;

    float *feat, *h1, *mean, *h2;
    uint32_t* wtf;
    cudaGetSymbolAddress((void**)&feat, g_feat);
    cudaGetSymbolAddress((void**)&h1, g_h1);
    cudaGetSymbolAddress((void**)&mean, g_mean);
    cudaGetSymbolAddress((void**)&h2, g_h2);
    cudaGetSymbolAddress((void**)&wtf, g_wtf);

    float* outp = (float*)d_out;            // [N, 2]
    float* em   = (float*)d_out + 2 * NN;   // [N, 160]

    // weight preconversion offsets: W_des | W_tw | W_txt | W_in | W_l | W_r | W_o1
    WConvArgs wa;
    wa.src[0] = W_des; wa.src[1] = W_tw; wa.src[2] = W_txt;
    wa.src[3] = W_in;  wa.src[4] = W_l;  wa.src[5] = W_r; wa.src[6] = W_o1;
    int sizes[7] = {24576, 24576, 24576, 25600, 25600, 25600, 25600};
    wa.off[0] = 0;
    for (int i = 0; i < 7; i++) wa.off[i + 1] = wa.off[i] + sizes[i];
    const uint32_t* tW_des = wtf + wa.off[0];
    const uint32_t* tW_tw  = wtf + wa.off[1];
    const uint32_t* tW_txt = wtf + wa.off[2];
    const uint32_t* tW_in  = wtf + wa.off[3];
    const uint32_t* tW_l   = wtf + wa.off[4];
    const uint32_t* tW_r   = wtf + wa.off[5];
    const uint32_t* tW_o1  = wtf + wa.off[6];
    wconv_kernel<<<(wa.off[7] + 255) / 256, 256>>>(wa);

    static bool attr_done = false;
    if (!attr_done) {
        cudaFuncSetAttribute(fw_gemm_p<false>, cudaFuncAttributeMaxDynamicSharedMemorySize, FWSMEM);
        cudaFuncSetAttribute(fw_gemm_p<true>,  cudaFuncAttributeMaxDynamicSharedMemorySize, FWSMEM);
        cudaFuncSetAttribute(fw_dual, cudaFuncAttributeMaxDynamicSharedMemorySize, FDSMEM);
        attr_done = true;
    }

    dim3 gProj((NN + 127) / 128, 1, 3);
    int gP = 148;                     // persistent grids
    int gNode8 = (NN + 7) / 8;
    int gEdge = (E + 255) / 256;

    // feature encoder -> g_feat [N,160] (cols: n|c|d|tw|t)
    feat_small_kernel<<<gNode8, 256>>>(num_prop, num_cat, W_np, b_np, W_nc, b_nc, feat);
    ProjArgs pa;
    pa.A[0] = des; pa.W[0] = tW_des; pa.b[0] = b_des; pa.off[0] = 64;
    pa.A[1] = tw;  pa.W[1] = tW_tw;  pa.b[1] = b_tw;  pa.off[1] = 96;
    pa.A[2] = x;   pa.W[2] = tW_txt; pa.b[2] = b_txt; pa.off[2] = 128;
    proj_kernel<<<gProj, 256>>>(pa, feat, NN, 768);

    // h1 = leaky(feat @ W_in + b_in)
    fw_gemm_p<true><<<gP, 512, FWSMEM>>>(feat, tW_in, b_in, h1, NN);

    // CSR build (per-launch, deterministic edge-dtype detection)
    detect_kernel<<<1, 256>>>(ei, E);
    zero_deg_kernel<<<(NN + 255) / 256, 256>>>();
    count_deg_kernel<<<gEdge, 256>>>(ei, E);
    scan_kernel<<<1, 1024>>>();
    fill_csr_kernel<<<gEdge, 256>>>(ei, E);

    // conv1: h2 = mean_nbr(h1 @ W_l) + (h1 @ W_r + b_l)   [linearity]
    fw_dual<<<gP, 512, FDSMEM>>>(h1, tW_l, tW_r, b_l, mean, feat, NN);
    agg_add_kernel<<<gNode8, 256>>>(mean, feat, h2);

    // conv2: h1 = mean_nbr(h2 @ W_l) + (h2 @ W_r + b_l)
    fw_dual<<<gP, 512, FDSMEM>>>(h2, tW_l, tW_r, b_l, mean, feat, NN);
    agg_add_kernel<<<gNode8, 256>>>(mean, feat, h1);

    // em = leaky(h1 @ W_o1 + b_o1), written directly into d_out
    fw_gemm_p<true><<<gP, 512, FWSMEM>>>(h1, tW_o1, b_o1, em, NN);

    // out = em @ W_o2 + b_o2
    out2_kernel<<<gNode8, 256>>>(em, W_o2, b_o2, outp);
}

// round 9
// speedup vs baseline: 1.1991x; 1.0095x over previous
#include <cuda_runtime.h>
#include <cstdint>

#define NN 50000
#define EMAX 500000
#define HID 160

// ---------------- scratch (static device globals; no allocation) ----------------
__device__ float g_feat[NN * HID];
__device__ float g_h1[NN * HID];
__device__ float g_mean[NN * HID];
__device__ float g_h2[NN * HID];
__device__ int g_deg[NN];
__device__ int g_offs[NN + 1];
__device__ int g_cursor[NN];
__device__ int g_csr[EMAX];
__device__ int g_is64;
// tf32-preconverted weights: W_des | W_tw | W_txt | W_in | W_l | W_r | W_o1
__device__ uint32_t g_wtf[3 * 24576 + 4 * 25600];

__device__ __forceinline__ float lrelu(float x) { return x > 0.f ? x : 0.01f * x; }

__device__ __forceinline__ uint32_t f2tf32(float x) {
    uint32_t u;
    asm("cvt.rna.tf32.f32 %0, %1;" : "=r"(u) : "f"(x));
    return u;
}
// round to tf32, keep as fp32 value (valid fp32 bit pattern)
__device__ __forceinline__ float rtf(float x) { return __uint_as_float(f2tf32(x)); }

__device__ __forceinline__ void cp16(void* dst_smem, const void* src, bool pred) {
    uint32_t d = (uint32_t)__cvta_generic_to_shared(dst_smem);
    int sz = pred ? 16 : 0;
    asm volatile("cp.async.cg.shared.global [%0], [%1], 16, %2;" :: "r"(d), "l"(src), "r"(sz));
}

// ---------------- weight preconversion (fp32 -> tf32 bits, RNA) ----------------
struct WConvArgs {
    const float* src[7];
    int off[8];
};

__global__ void wconv_kernel(WConvArgs a) {
    int i = blockIdx.x * 256 + threadIdx.x;
    #pragma unroll
    for (int s = 0; s < 7; s++) {
        if (i >= a.off[s] && i < a.off[s + 1])
            g_wtf[i] = f2tf32(a.src[s][i - a.off[s]]);
    }
}

// Edge index may be int64 (reference) or int32 (JAX canonicalization).
__device__ __forceinline__ int edge_val(const void* ei, int idx) {
    if (g_is64) return (int)((const long long*)ei)[idx];
    return ((const int*)ei)[idx];
}

__global__ void detect_kernel(const void* ei, int E) {
    __shared__ int any_hi;
    int t = threadIdx.x;
    if (t == 0) any_hi = 0;
    __syncthreads();
    const unsigned long long* p = (const unsigned long long*)ei;
    int n = E < 1024 ? E : 1024;
    unsigned long long acc = 0;
    for (int i = t; i < n; i += 256) acc |= p[i];
    if (acc > 0xFFFFFFFFull) atomicOr(&any_hi, 1);
    __syncthreads();
    if (t == 0) g_is64 = any_hi ? 0 : 1;
}

// ============ fw_gemm_p: persistent full-W-resident GEMM, K=N=160 ============
// C = leaky?(A @ W + bias), optionally tf32-rounded output (ROUND).
// A is ASSUMED tf32-rounded already -> fragments load raw bits (no cvt).
// grid=148; 512 thr = 4m x 4n warps, warp tile 32x40; 4-stage A ring.
#define FW_WWORDS (160 * 168)
#define FWSMEM (FW_WWORDS * 4 + 4 * 128 * 36 * 4)   // 181248

template <bool LEAKY, bool ROUND>
__global__ void __launch_bounds__(512, 1) fw_gemm_p(
    const float* __restrict__ A, const uint32_t* __restrict__ W,
    const float* __restrict__ bias, float* __restrict__ C, int M)
{
    extern __shared__ __align__(16) char smraw[];
    uint32_t (*Ws)[168] = reinterpret_cast<uint32_t (*)[168]>(smraw);
    float (*As)[128][36] = reinterpret_cast<float (*)[128][36]>(smraw + FW_WWORDS * 4);

    const int t = threadIdx.x;
    const int warp = t >> 5, lane = t & 31;
    const int mwarp = warp >> 2, nwarp = warp & 3;
    const int g = lane >> 2, tg = lane & 3;
    const int warpRow = mwarp * 32, ncol0 = nwarp * 40;
    const int arow = t >> 1, acol = (t & 1) * 16;

    for (int i = t; i < 6400; i += 512) {
        int row = i / 40, c4 = (i % 40) * 4;
        cp16(&Ws[row][c4], W + (size_t)row * HID + c4, true);
    }

    const int ntiles = (M + 127) >> 7;
    for (int tile = blockIdx.x; tile < ntiles; tile += gridDim.x) {
        const int blockRow = tile << 7;
        auto issueA = [&](int c) {
            if (c <= 4 && t < 256) {
                int buf = c & 3;
                int gr = blockRow + arow;
                const float* src = A + (size_t)gr * HID + c * 32 + acol;
                bool p = gr < M;
                cp16(&As[buf][arow][acol], src, p);
                cp16(&As[buf][arow][acol + 4], src + 4, p);
                cp16(&As[buf][arow][acol + 8], src + 8, p);
                cp16(&As[buf][arow][acol + 12], src + 12, p);
            }
        };
        issueA(0); asm volatile("cp.async.commit_group;");
        issueA(1); asm volatile("cp.async.commit_group;");
        issueA(2); asm volatile("cp.async.commit_group;");

        float acc[2][5][4] = {};
        #pragma unroll
        for (int c = 0; c < 5; c++) {
            asm volatile("cp.async.wait_group 2;");
            __syncthreads();
            const int buf = c & 3;
            #pragma unroll
            for (int kk = 0; kk < 32; kk += 8) {
                const int gk = c * 32 + kk;
                uint32_t a[2][4];
                #pragma unroll
                for (int mt = 0; mt < 2; mt++) {
                    const int r = warpRow + mt * 16 + g;
                    a[mt][0] = __float_as_uint(As[buf][r][kk + tg]);
                    a[mt][1] = __float_as_uint(As[buf][r + 8][kk + tg]);
                    a[mt][2] = __float_as_uint(As[buf][r][kk + tg + 4]);
                    a[mt][3] = __float_as_uint(As[buf][r + 8][kk + tg + 4]);
                }
                #pragma unroll
                for (int nt = 0; nt < 5; nt++) {
                    uint32_t b0 = Ws[gk + tg][ncol0 + nt * 8 + g];
                    uint32_t b1 = Ws[gk + tg + 4][ncol0 + nt * 8 + g];
                    #pragma unroll
                    for (int mt = 0; mt < 2; mt++) {
                        float* cc = acc[mt][nt];
                        asm volatile(
                            "mma.sync.aligned.m16n8k8.row.col.f32.tf32.tf32.f32 "
                            "{%0,%1,%2,%3}, {%4,%5,%6,%7}, {%8,%9}, {%0,%1,%2,%3};"
                            : "+f"(cc[0]), "+f"(cc[1]), "+f"(cc[2]), "+f"(cc[3])
                            : "r"(a[mt][0]), "r"(a[mt][1]), "r"(a[mt][2]), "r"(a[mt][3]),
                              "r"(b0), "r"(b1));
                    }
                }
            }
            issueA(c + 3);
            asm volatile("cp.async.commit_group;");
        }

        #pragma unroll
        for (int nt = 0; nt < 5; nt++) {
            int lc = ncol0 + nt * 8 + 2 * tg;
            float b0 = bias[lc];
            float b1 = bias[lc + 1];
            #pragma unroll
            for (int mt = 0; mt < 2; mt++) {
                float* cc = acc[mt][nt];
                int r0 = blockRow + warpRow + mt * 16 + g;
                int r1 = r0 + 8;
                float v00 = cc[0] + b0, v01 = cc[1] + b1;
                float v10 = cc[2] + b0, v11 = cc[3] + b1;
                if (LEAKY) {
                    v00 = lrelu(v00); v01 = lrelu(v01);
                    v10 = lrelu(v10); v11 = lrelu(v11);
                }
                if (ROUND) {
                    v00 = rtf(v00); v01 = rtf(v01);
                    v10 = rtf(v10); v11 = rtf(v11);
                }
                if (r0 < M)
                    *(float2*)(C + (size_t)r0 * HID + lc) = make_float2(v00, v01);
                if (r1 < M)
                    *(float2*)(C + (size_t)r1 * HID + lc) = make_float2(v10, v11);
            }
        }
        __syncthreads();   // protect A-ring reuse across tiles
    }
}

// ============ fw_dual: persistent dual-W GEMM for SAGE conv ============
// C1 = A @ W_l ; C2 = A @ W_r + bias. Both W resident (Ws[160][328]).
// A assumed tf32-rounded (raw fragment loads). BM=64, 2-stage A ring.
#define FD_STRIDE 328
#define FD_WWORDS (160 * FD_STRIDE)
#define FDSMEM (FD_WWORDS * 4 + 2 * 64 * 36 * 4)     // 228352

__global__ void __launch_bounds__(512, 1) fw_dual(
    const float* __restrict__ A, const uint32_t* __restrict__ Wl,
    const uint32_t* __restrict__ Wr, const float* __restrict__ bias,
    float* __restrict__ C1, float* __restrict__ C2, int M)
{
    extern __shared__ __align__(16) char smraw[];
    uint32_t (*Ws)[FD_STRIDE] = reinterpret_cast<uint32_t (*)[FD_STRIDE]>(smraw);
    float (*As)[64][36] = reinterpret_cast<float (*)[64][36]>(smraw + FD_WWORDS * 4);

    const int t = threadIdx.x;
    const int warp = t >> 5, lane = t & 31;
    const int mwarp = warp >> 3, nwarp = warp & 7;
    const int g = lane >> 2, tg = lane & 3;
    const int warpRow = mwarp * 32, ncol0 = nwarp * 40;
    const int arow = t >> 3, acol = (t & 7) * 4;

    for (int i = t; i < 12800; i += 512) {
        int row = i / 80, c4 = (i % 80) * 4;
        const uint32_t* src = (c4 < 160) ? (Wl + (size_t)row * HID + c4)
                                         : (Wr + (size_t)row * HID + (c4 - 160));
        cp16(&Ws[row][c4], src, true);
    }

    const int ntiles = (M + 63) >> 6;
    for (int tile = blockIdx.x; tile < ntiles; tile += gridDim.x) {
        const int blockRow = tile << 6;
        auto issueA = [&](int c) {
            if (c <= 4) {
                int buf = c & 1;
                int gr = blockRow + arow;
                const float* src = A + (size_t)gr * HID + c * 32 + acol;
                cp16(&As[buf][arow][acol], src, gr < M);
            }
        };
        issueA(0); asm volatile("cp.async.commit_group;");
        issueA(1); asm volatile("cp.async.commit_group;");

        float acc[2][5][4] = {};
        #pragma unroll
        for (int c = 0; c < 5; c++) {
            asm volatile("cp.async.wait_group 1;");
            __syncthreads();
            const int buf = c & 1;
            #pragma unroll
            for (int kk = 0; kk < 32; kk += 8) {
                const int gk = c * 32 + kk;
                uint32_t a[2][4];
                #pragma unroll
                for (int mt = 0; mt < 2; mt++) {
                    const int r = warpRow + mt * 16 + g;
                    a[mt][0] = __float_as_uint(As[buf][r][kk + tg]);
                    a[mt][1] = __float_as_uint(As[buf][r + 8][kk + tg]);
                    a[mt][2] = __float_as_uint(As[buf][r][kk + tg + 4]);
                    a[mt][3] = __float_as_uint(As[buf][r + 8][kk + tg + 4]);
                }
                #pragma unroll
                for (int nt = 0; nt < 5; nt++) {
                    uint32_t b0 = Ws[gk + tg][ncol0 + nt * 8 + g];
                    uint32_t b1 = Ws[gk + tg + 4][ncol0 + nt * 8 + g];
                    #pragma unroll
                    for (int mt = 0; mt < 2; mt++) {
                        float* cc = acc[mt][nt];
                        asm volatile(
                            "mma.sync.aligned.m16n8k8.row.col.f32.tf32.tf32.f32 "
                            "{%0,%1,%2,%3}, {%4,%5,%6,%7}, {%8,%9}, {%0,%1,%2,%3};"
                            : "+f"(cc[0]), "+f"(cc[1]), "+f"(cc[2]), "+f"(cc[3])
                            : "r"(a[mt][0]), "r"(a[mt][1]), "r"(a[mt][2]), "r"(a[mt][3]),
                              "r"(b0), "r"(b1));
                    }
                }
            }
            __syncthreads();   // 2-stage ring: reads of buf done before re-issue
            issueA(c + 2);
            asm volatile("cp.async.commit_group;");
        }

        float* Cout = (nwarp < 4) ? C1 : C2;
        const int cb = (nwarp < 4) ? ncol0 : (ncol0 - 160);
        const bool useb = (nwarp >= 4);
        #pragma unroll
        for (int nt = 0; nt < 5; nt++) {
            int lc = cb + nt * 8 + 2 * tg;
            float b0 = useb ? bias[lc] : 0.f;
            float b1 = useb ? bias[lc + 1] : 0.f;
            #pragma unroll
            for (int mt = 0; mt < 2; mt++) {
                float* cc = acc[mt][nt];
                int r0 = blockRow + warpRow + mt * 16 + g;
                int r1 = r0 + 8;
                if (r0 < M)
                    *(float2*)(Cout + (size_t)r0 * HID + lc) = make_float2(cc[0] + b0, cc[1] + b1);
                if (r1 < M)
                    *(float2*)(Cout + (size_t)r1 * HID + lc) = make_float2(cc[2] + b0, cc[3] + b1);
            }
        }
        __syncthreads();   // protect A-ring reuse across tiles
    }
}

// ============ projection GEMM (768->32): split-K core; A cvt at frag load ============
struct ProjArgs {
    const float* A[3];
    const uint32_t* W[3];
    const float* b[3];
    int off[3];
};

__global__ void __launch_bounds__(256) proj_kernel(ProjArgs pa, float* __restrict__ C,
                                                   int M, int K)
{
    __shared__ __align__(16) float As[2][128][36];
    __shared__ __align__(16) uint32_t Ws[2][32][40];

    const int z = blockIdx.z;
    const float* __restrict__ A = pa.A[z];
    const uint32_t* __restrict__ W = pa.W[z];
    const float* __restrict__ bias = pa.b[z];
    const int cOff = pa.off[z];

    const int t = threadIdx.x;
    const int warp = t >> 5;
    const int lane = t & 31;
    const int mwarp = warp & 3;
    const int kg = warp >> 2;
    const int g = lane >> 2;
    const int tg = lane & 3;
    const int blockRow = blockIdx.x * 128;
    const int warpRow = mwarp * 32;

    const int arow = t >> 1;
    const int acol = (t & 1) * 16;
    const int wrow = t >> 3;
    const int wcol = (t & 7) * 4;

    const int nchunks = K >> 5;

    auto issue = [&](int c) {
        int k0 = c << 5;
        int buf = c & 1;
        int gr = blockRow + arow;
        const float* src = A + (size_t)gr * K + k0 + acol;
        bool p = gr < M;
        #pragma unroll
        for (int j = 0; j < 4; j++)
            cp16(&As[buf][arow][acol + j * 4], src + j * 4, p);
        const uint32_t* wsrc = W + (size_t)(k0 + wrow) * 32 + wcol;
        cp16(&Ws[buf][wrow][wcol], wsrc, true);
        asm volatile("cp.async.commit_group;");
    };

    float acc[2][4][4] = {};

    issue(0);
    for (int c = 0; c < nchunks; c++) {
        if (c + 1 < nchunks) {
            issue(c + 1);
            asm volatile("cp.async.wait_group 1;");
        } else {
            asm volatile("cp.async.wait_group 0;");
        }
        __syncthreads();
        const int buf = c & 1;
        #pragma unroll
        for (int s = 0; s < 2; s++) {
            const int kk = kg * 16 + s * 8;
            uint32_t a[2][4];
            #pragma unroll
            for (int mt = 0; mt < 2; mt++) {
                const int r = warpRow + mt * 16 + g;
                a[mt][0] = f2tf32(As[buf][r][kk + tg]);
                a[mt][1] = f2tf32(As[buf][r + 8][kk + tg]);
                a[mt][2] = f2tf32(As[buf][r][kk + tg + 4]);
                a[mt][3] = f2tf32(As[buf][r + 8][kk + tg + 4]);
            }
            #pragma unroll
            for (int nt = 0; nt < 4; nt++) {
                uint32_t b0 = Ws[buf][kk + tg][nt * 8 + g];
                uint32_t b1 = Ws[buf][kk + tg + 4][nt * 8 + g];
                #pragma unroll
                for (int mt = 0; mt < 2; mt++) {
                    float* cc = acc[mt][nt];
                    asm volatile(
                        "mma.sync.aligned.m16n8k8.row.col.f32.tf32.tf32.f32 "
                        "{%0,%1,%2,%3}, {%4,%5,%6,%7}, {%8,%9}, {%0,%1,%2,%3};"
                        : "+f"(cc[0]), "+f"(cc[1]), "+f"(cc[2]), "+f"(cc[3])
                        : "r"(a[mt][0]), "r"(a[mt][1]), "r"(a[mt][2]), "r"(a[mt][3]),
                          "r"(b0), "r"(b1));
                }
            }
        }
        __syncthreads();
    }

    float* scratch = &As[0][0][0];
    if (kg == 1) {
        #pragma unroll
        for (int mt = 0; mt < 2; mt++)
            #pragma unroll
            for (int nt = 0; nt < 4; nt++)
                #pragma unroll
                for (int i = 0; i < 4; i++) {
                    int combo = (mt * 4 + nt) * 4 + i;
                    scratch[combo * 128 + mwarp * 32 + lane] = acc[mt][nt][i];
                }
    }
    __syncthreads();

    if (kg == 0) {
        #pragma unroll
        for (int nt = 0; nt < 4; nt++) {
            int lc = nt * 8 + 2 * tg;
            float b0 = bias[lc];
            float b1 = bias[lc + 1];
            #pragma unroll
            for (int mt = 0; mt < 2; mt++) {
                float* cc = acc[mt][nt];
                int base = ((mt * 4 + nt) * 4) * 128 + mwarp * 32 + lane;
                float v00 = rtf(lrelu(cc[0] + scratch[base]       + b0));
                float v01 = rtf(lrelu(cc[1] + scratch[base + 128] + b1));
                float v10 = rtf(lrelu(cc[2] + scratch[base + 256] + b0));
                float v11 = rtf(lrelu(cc[3] + scratch[base + 384] + b1));
                int r0 = blockRow + warpRow + mt * 16 + g;
                int r1 = r0 + 8;
                if (r0 < M)
                    *(float2*)(C + (size_t)r0 * HID + cOff + lc) = make_float2(v00, v01);
                if (r1 < M)
                    *(float2*)(C + (size_t)r1 * HID + cOff + lc) = make_float2(v10, v11);
            }
        }
    }
}

// ---------------- small feature projections (tf32-rounded outputs) ----------------
__global__ void __launch_bounds__(256) feat_small_kernel(
    const float* __restrict__ np, const float* __restrict__ nc,
    const float* __restrict__ Wnp, const float* __restrict__ bnp,
    const float* __restrict__ Wnc, const float* __restrict__ bnc,
    float* __restrict__ out)
{
    __shared__ float sWnp[6 * 32];
    __shared__ float sWnc[11 * 32];
    __shared__ float sb[64];
    int t = threadIdx.x;
    for (int i = t; i < 192; i += 256) sWnp[i] = Wnp[i];
    for (int i = t; i < 352; i += 256) sWnc[i] = Wnc[i];
    if (t < 32) sb[t] = bnp[t];
    else if (t < 64) sb[t] = bnc[t - 32];
    __syncthreads();

    int node = blockIdx.x * 8 + (t >> 5);
    int lane = t & 31;
    if (node >= NN) return;

    float a = sb[lane], c = sb[32 + lane];
    #pragma unroll
    for (int k = 0; k < 6; k++) a += np[(size_t)node * 6 + k] * sWnp[k * 32 + lane];
    #pragma unroll
    for (int k = 0; k < 11; k++) c += nc[(size_t)node * 11 + k] * sWnc[k * 32 + lane];
    out[(size_t)node * HID + lane] = rtf(lrelu(a));
    out[(size_t)node * HID + 32 + lane] = rtf(lrelu(c));
}

// ---------------- CSR build ----------------
__global__ void zero_deg_kernel() {
    int i = blockIdx.x * blockDim.x + threadIdx.x;
    if (i < NN) g_deg[i] = 0;
}

__global__ void count_deg_kernel(const void* __restrict__ ei, int E) {
    int e = blockIdx.x * blockDim.x + threadIdx.x;
    if (e < E) atomicAdd(&g_deg[edge_val(ei, E + e)], 1);
}

__global__ void scan_kernel() {
    __shared__ int part[1024];
    int t = threadIdx.x;
    const int chunk = (NN + 1023) / 1024;
    int s0 = t * chunk;
    int s1 = s0 + chunk; if (s1 > NN) s1 = NN; if (s0 > NN) s0 = NN;
    int s = 0;
    for (int i = s0; i < s1; i++) s += g_deg[i];
    part[t] = s;
    __syncthreads();
    for (int d = 1; d < 1024; d <<= 1) {
        int v = (t >= d) ? part[t - d] : 0;
        __syncthreads();
        part[t] += v;
        __syncthreads();
    }
    int excl = t ? part[t - 1] : 0;
    for (int i = s0; i < s1; i++) {
        g_offs[i] = excl;
        g_cursor[i] = excl;
        excl += g_deg[i];
    }
    if (t == 1023) g_offs[NN] = part[1023];
}

__global__ void fill_csr_kernel(const void* __restrict__ ei, int E) {
    int e = blockIdx.x * blockDim.x + threadIdx.x;
    if (e < E) {
        int d = edge_val(ei, E + e);
        int p = atomicAdd(&g_cursor[d], 1);
        g_csr[p] = edge_val(ei, e);
    }
}

// -------- fused mean-aggregate + add (float4 gathers, tf32-rounded output) --------
// out = rtf( mean_nbr(t1) + t2 )
__global__ void __launch_bounds__(256) agg_add_kernel(
    const float* __restrict__ t1, const float* __restrict__ t2,
    float* __restrict__ out)
{
    int w = (blockIdx.x * blockDim.x + threadIdx.x) >> 5;
    int lane = threadIdx.x & 31;
    if (w >= NN) return;
    int beg = g_offs[w], end = g_offs[w + 1];
    const bool tail = lane < 8;

    float4 s0 = make_float4(0.f, 0.f, 0.f, 0.f);
    float4 s1 = make_float4(0.f, 0.f, 0.f, 0.f);

    int e = beg;
    for (; e + 2 <= end; e += 2) {
        const float4* ra = (const float4*)(t1 + (size_t)g_csr[e] * HID);
        const float4* rb = (const float4*)(t1 + (size_t)g_csr[e + 1] * HID);
        float4 va = ra[lane], vb = rb[lane];
        s0.x += va.x + vb.x; s0.y += va.y + vb.y;
        s0.z += va.z + vb.z; s0.w += va.w + vb.w;
        if (tail) {
            float4 ua = ra[32 + lane], ub = rb[32 + lane];
            s1.x += ua.x + ub.x; s1.y += ua.y + ub.y;
            s1.z += ua.z + ub.z; s1.w += ua.w + ub.w;
        }
    }
    if (e < end) {
        const float4* ra = (const float4*)(t1 + (size_t)g_csr[e] * HID);
        float4 va = ra[lane];
        s0.x += va.x; s0.y += va.y; s0.z += va.z; s0.w += va.w;
        if (tail) {
            float4 ua = ra[32 + lane];
            s1.x += ua.x; s1.y += ua.y; s1.z += ua.z; s1.w += ua.w;
        }
    }

    int deg = end - beg;
    float inv = 1.f / (float)(deg > 0 ? deg : 1);
    const float4* b = (const float4*)(t2 + (size_t)w * HID);
    float4* m = (float4*)(out + (size_t)w * HID);

    float4 bv = b[lane];
    float4 o;
    o.x = rtf(s0.x * inv + bv.x);
    o.y = rtf(s0.y * inv + bv.y);
    o.z = rtf(s0.z * inv + bv.z);
    o.w = rtf(s0.w * inv + bv.w);
    m[lane] = o;
    if (tail) {
        float4 bu = b[32 + lane];
        float4 p;
        p.x = rtf(s1.x * inv + bu.x);
        p.y = rtf(s1.y * inv + bu.y);
        p.z = rtf(s1.z * inv + bu.z);
        p.w = rtf(s1.w * inv + bu.w);
        m[32 + lane] = p;
    }
}

// ---------------- final 160->2 head: one warp per node ----------------
__global__ void __launch_bounds__(256) out2_kernel(
    const float* __restrict__ em, const float* __restrict__ W,
    const float* __restrict__ b, float* __restrict__ out)
{
    __shared__ float sW[320];
    int t = threadIdx.x;
    for (int i = t; i < 320; i += 256) sW[i] = W[i];
    __syncthreads();
    int node = blockIdx.x * 8 + (t >> 5);
    int lane = t & 31;
    if (node >= NN) return;
    float a0 = 0.f, a1 = 0.f;
    #pragma unroll
    for (int c = 0; c < 5; c++) {
        int k = lane + 32 * c;
        float v = em[(size_t)node * HID + k];
        a0 += v * sW[k * 2];
        a1 += v * sW[k * 2 + 1];
    }
    #pragma unroll
    for (int o = 16; o > 0; o >>= 1) {
        a0 += __shfl_down_sync(0xffffffffu, a0, o);
        a1 += __shfl_down_sync(0xffffffffu, a1, o);
    }
    if (lane == 0) {
        out[(size_t)node * 2]     = a0 + b[0];
        out[(size_t)node * 2 + 1] = a1 + b[1];
    }
}

// ---------------- launch ----------------
extern "C" void kernel_launch(void* const* d_in, const int* in_sizes, int n_in,
                              void* d_out, int out_size)
{
    const float* x        = (const float*)d_in[0];
    const void*  ei       = d_in[1];
    const float* num_prop = (const float*)d_in[2];
    const float* num_cat  = (const float*)d_in[3];
    const float* des      = (const float*)d_in[4];
    const float* tw       = (const float*)d_in[5];
    const float* W_des = (const float*)d_in[6];  const float* b_des = (const float*)d_in[7];
    const float* W_tw  = (const float*)d_in[8];  const float* b_tw  = (const float*)d_in[9];
    const float* W_txt = (const float*)d_in[10]; const float* b_txt = (const float*)d_in[11];
    const float* W_np  = (const float*)d_in[12]; const float* b_np  = (const float*)d_in[13];
    const float* W_nc  = (const float*)d_in[14]; const float* b_nc  = (const float*)d_in[15];
    const float* W_in  = (const float*)d_in[16]; const float* b_in  = (const float*)d_in[17];
    const float* W_l   = (const float*)d_in[18]; const float* b_l   = (const float*)d_in[19];
    const float* W_r   = (const float*)d_in[20];
    const float* W_o1  = (const float*)d_in[21]; const float* b_o1  = (const float*)d_in[22];
    const float* W_o2  = (const float*)d_in[23]; const float* b_o2  = (const float*)d_in[24];

    int E = in_sizes[1] / 2;
    if (E > EMAX) E = EMAX;

    float *feat, *h1, *mean, *h2;
    uint32_t* wtf;
    cudaGetSymbolAddress((void**)&feat, g_feat);
    cudaGetSymbolAddress((void**)&h1, g_h1);
    cudaGetSymbolAddress((void**)&mean, g_mean);
    cudaGetSymbolAddress((void**)&h2, g_h2);
    cudaGetSymbolAddress((void**)&wtf, g_wtf);

    float* outp = (float*)d_out;            // [N, 2]
    float* em   = (float*)d_out + 2 * NN;   // [N, 160]

    WConvArgs wa;
    wa.src[0] = W_des; wa.src[1] = W_tw; wa.src[2] = W_txt;
    wa.src[3] = W_in;  wa.src[4] = W_l;  wa.src[5] = W_r; wa.src[6] = W_o1;
    int sizes[7] = {24576, 24576, 24576, 25600, 25600, 25600, 25600};
    wa.off[0] = 0;
    for (int i = 0; i < 7; i++) wa.off[i + 1] = wa.off[i] + sizes[i];
    const uint32_t* tW_des = wtf + wa.off[0];
    const uint32_t* tW_tw  = wtf + wa.off[1];
    const uint32_t* tW_txt = wtf + wa.off[2];
    const uint32_t* tW_in  = wtf + wa.off[3];
    const uint32_t* tW_l   = wtf + wa.off[4];
    const uint32_t* tW_r   = wtf + wa.off[5];
    const uint32_t* tW_o1  = wtf + wa.off[6];
    wconv_kernel<<<(wa.off[7] + 255) / 256, 256>>>(wa);

    static bool attr_done = false;
    if (!attr_done) {
        cudaFuncSetAttribute((const void*)fw_gemm_p<true, true>,
                             cudaFuncAttributeMaxDynamicSharedMemorySize, FWSMEM);
        cudaFuncSetAttribute((const void*)fw_gemm_p<true, false>,
                             cudaFuncAttributeMaxDynamicSharedMemorySize, FWSMEM);
        cudaFuncSetAttribute((const void*)fw_dual,
                             cudaFuncAttributeMaxDynamicSharedMemorySize, FDSMEM);
        attr_done = true;
    }

    dim3 gProj((NN + 127) / 128, 1, 3);
    int gP = 148;
    int gNode8 = (NN + 7) / 8;
    int gEdge = (E + 255) / 256;

    // feature encoder -> g_feat [N,160] (cols: n|c|d|tw|t), tf32-rounded
    feat_small_kernel<<<gNode8, 256>>>(num_prop, num_cat, W_np, b_np, W_nc, b_nc, feat);
    ProjArgs pa;
    pa.A[0] = des; pa.W[0] = tW_des; pa.b[0] = b_des; pa.off[0] = 64;
    pa.A[1] = tw;  pa.W[1] = tW_tw;  pa.b[1] = b_tw;  pa.off[1] = 96;
    pa.A[2] = x;   pa.W[2] = tW_txt; pa.b[2] = b_txt; pa.off[2] = 128;
    proj_kernel<<<gProj, 256>>>(pa, feat, NN, 768);

    // h1 = rtf(leaky(feat @ W_in + b_in))  -- rounded: consumed by MMA kernels
    fw_gemm_p<true, true><<<gP, 512, FWSMEM>>>(feat, tW_in, b_in, h1, NN);

    // CSR build
    detect_kernel<<<1, 256>>>(ei, E);
    zero_deg_kernel<<<(NN + 255) / 256, 256>>>();
    count_deg_kernel<<<gEdge, 256>>>(ei, E);
    scan_kernel<<<1, 1024>>>();
    fill_csr_kernel<<<gEdge, 256>>>(ei, E);

    // conv1: h2 = rtf( mean_nbr(h1 @ W_l) + (h1 @ W_r + b_l) )
    fw_dual<<<gP, 512, FDSMEM>>>(h1, tW_l, tW_r, b_l, mean, feat, NN);
    agg_add_kernel<<<gNode8, 256>>>(mean, feat, h2);

    // conv2: h1 = rtf( mean_nbr(h2 @ W_l) + (h2 @ W_r + b_l) )
    fw_dual<<<gP, 512, FDSMEM>>>(h2, tW_l, tW_r, b_l, mean, feat, NN);
    agg_add_kernel<<<gNode8, 256>>>(mean, feat, h1);

    // em = leaky(h1 @ W_o1 + b_o1)  -- NOT rounded (graded output)
    fw_gemm_p<true, false><<<gP, 512, FWSMEM>>>(h1, tW_o1, b_o1, em, NN);

    // out = em @ W_o2 + b_o2
    out2_kernel<<<gNode8, 256>>>(em, W_o2, b_o2, outp);
}

// round 10
// speedup vs baseline: 1.2073x; 1.0069x over previous
#include <cuda_runtime.h>
#include <cstdint>

#define NN 50000
#define NPAD 50048          // padded row count (782 * 64)
#define EMAX 500000
#define HID 160
#define LD 164              // row stride of intermediates: 164 % 32 == 4 -> conflict-free frags

// ---------------- scratch (static device globals; no allocation) ----------------
__device__ float g_feat[NPAD * LD];
__device__ float g_h1[NPAD * LD];
__device__ float g_mean[NPAD * LD];
__device__ float g_h2[NPAD * LD];
__device__ int g_deg[NN];
__device__ int g_offs[NN + 1];
__device__ int g_cursor[NN];
__device__ int g_csr[EMAX];
__device__ int g_is64;
// padded tf32 weights: 3x proj [768][40] + 4x hid [160][168]
__device__ uint32_t g_wtf[3 * 768 * 40 + 4 * 160 * 168];

__device__ __forceinline__ float lrelu(float x) { return x > 0.f ? x : 0.01f * x; }

__device__ __forceinline__ uint32_t f2tf32(float x) {
    uint32_t u;
    asm("cvt.rna.tf32.f32 %0, %1;" : "=r"(u) : "f"(x));
    return u;
}
__device__ __forceinline__ float rtf(float x) { return __uint_as_float(f2tf32(x)); }

__device__ __forceinline__ uint32_t smem_u32(const void* p) {
    return (uint32_t)__cvta_generic_to_shared(p);
}

// ---------------- mbarrier + bulk-copy primitives ----------------
#define MBAR_INIT(addr, cnt) \
    asm volatile("mbarrier.init.shared.b64 [%0], %1;" :: "r"(addr), "r"(cnt) : "memory")
#define MBAR_EXPECT(addr, bytes) \
    asm volatile("mbarrier.arrive.expect_tx.shared.b64 _, [%0], %1;" :: "r"(addr), "r"(bytes) : "memory")
#define MBAR_WAITP(addr, ph) do { \
    asm volatile( \
        "{\n\t.reg .pred P;\n" \
        "WAITL_%=:\n\t" \
        "mbarrier.try_wait.parity.acquire.cta.shared::cta.b64 P, [%0], %1, 0x989680;\n\t" \
        "@P bra.uni WAITD_%=;\n\t" \
        "bra.uni WAITL_%=;\n" \
        "WAITD_%=:\n\t}" \
        :: "r"(addr), "r"((uint32_t)(ph)) : "memory"); } while (0)

__device__ __forceinline__ void bulkcp(uint32_t dst_smem, const void* src,
                                       uint32_t bytes, uint32_t mbar) {
    asm volatile(
        "cp.async.bulk.shared::cluster.global.mbarrier::complete_tx::bytes "
        "[%0], [%1], %2, [%3];"
        :: "r"(dst_smem), "l"(src), "r"(bytes), "r"(mbar) : "memory");
}

// ---------------- weight preconversion into PADDED layouts ----------------
struct WC {
    const float* src[7];
    int doff[7], cols[7], ldd[7], cum[8];
};

__global__ void wconv_kernel(WC a) {
    int i = blockIdx.x * 256 + threadIdx.x;
    #pragma unroll
    for (int s = 0; s < 7; s++) {
        if (i >= a.cum[s] && i < a.cum[s + 1]) {
            int j = i - a.cum[s];
            int row = j / a.cols[s], col = j % a.cols[s];
            g_wtf[a.doff[s] + row * a.ldd[s] + col] = f2tf32(a.src[s][j]);
        }
    }
}

// Edge index may be int64 (reference) or int32 (JAX canonicalization).
__device__ __forceinline__ int edge_val(const void* ei, int idx) {
    if (g_is64) return (int)((const long long*)ei)[idx];
    return ((const int*)ei)[idx];
}

__global__ void detect_kernel(const void* ei, int E) {
    __shared__ int any_hi;
    int t = threadIdx.x;
    if (t == 0) any_hi = 0;
    __syncthreads();
    const unsigned long long* p = (const unsigned long long*)ei;
    int n = E < 1024 ? E : 1024;
    unsigned long long acc = 0;
    for (int i = t; i < n; i += 256) acc |= p[i];
    if (acc > 0xFFFFFFFFull) atomicOr(&any_hi, 1);
    __syncthreads();
    if (t == 0) g_is64 = any_hi ? 0 : 1;
}

// ============ fw_gemm_p: persistent full-W GEMM, bulk-copy loads ============
// C[:, :160] = leaky?(round?( A[M,LD] @ W[160,160] + bias )); A rows stride LD.
// W bulk-loaded once (gmem padded stride 168). A: 2-slot ring of 64-row tiles
// (one contiguous 41,984B bulk per tile). 512 thr = 4m x 4n warps, 16m x 40n tile.
#define FW_W_BYTES (160 * 168 * 4)          // 107520
#define FW_TILE_BYTES (64 * LD * 4)         // 41984
#define FW_SMEM (128 + FW_W_BYTES + 2 * FW_TILE_BYTES)   // 191616

template <bool LEAKY, bool ROUND>
__global__ void __launch_bounds__(512, 1) fw_gemm_p(
    const float* __restrict__ A, const uint32_t* __restrict__ W,
    const float* __restrict__ bias, float* __restrict__ C, int ldC, int M)
{
    extern __shared__ __align__(16) char sm[];
    const uint32_t sb = smem_u32(sm);
    const uint32_t bar_w = sb, bar_f0 = sb + 8, bar_f1 = sb + 16;
    const uint32_t ws_addr = sb + 128;
    const uint32_t as_addr = ws_addr + FW_W_BYTES;
    uint32_t (*Ws)[168] = reinterpret_cast<uint32_t (*)[168]>(sm + 128);
    float (*As)[64][LD] = reinterpret_cast<float (*)[64][LD]>(sm + 128 + FW_W_BYTES);

    const int t = threadIdx.x;
    if (t == 0) {
        MBAR_INIT(bar_w, 1);
        MBAR_INIT(bar_f0, 1);
        MBAR_INIT(bar_f1, 1);
    }
    __syncthreads();
    if (t == 0) {
        MBAR_EXPECT(bar_w, FW_W_BYTES);
        bulkcp(ws_addr, W, FW_W_BYTES, bar_w);
    }

    const int ntiles = (M + 63) >> 6;        // buffers padded to NPAD rows
    int tiles[8];
    int nloc = 0;
    for (int tt = blockIdx.x; tt < ntiles; tt += gridDim.x) tiles[nloc++] = tt;

    auto issue = [&](int i) {
        if (i < nloc && t == 0) {
            uint32_t bar = (i & 1) ? bar_f1 : bar_f0;
            MBAR_EXPECT(bar, FW_TILE_BYTES);
            bulkcp(as_addr + (uint32_t)(i & 1) * FW_TILE_BYTES,
                   A + (size_t)tiles[i] * 64 * LD, FW_TILE_BYTES, bar);
        }
    };
    issue(0);
    issue(1);

    const int warp = t >> 5, lane = t & 31;
    const int mw = warp >> 2, nw = warp & 3;
    const int g = lane >> 2, tg = lane & 3;
    const int ncol0 = nw * 40;
    const int r = mw * 16 + g;
    bool wdone = false;

    for (int i = 0; i < nloc; i++) {
        MBAR_WAITP((i & 1) ? bar_f1 : bar_f0, (i >> 1) & 1);
        if (!wdone) { MBAR_WAITP(bar_w, 0); wdone = true; }
        const int buf = i & 1;

        float acc[5][4] = {};
        #pragma unroll
        for (int kk = 0; kk < 160; kk += 8) {
            uint32_t a0 = __float_as_uint(As[buf][r][kk + tg]);
            uint32_t a1 = __float_as_uint(As[buf][r + 8][kk + tg]);
            uint32_t a2 = __float_as_uint(As[buf][r][kk + tg + 4]);
            uint32_t a3 = __float_as_uint(As[buf][r + 8][kk + tg + 4]);
            #pragma unroll
            for (int nt = 0; nt < 5; nt++) {
                uint32_t b0 = Ws[kk + tg][ncol0 + nt * 8 + g];
                uint32_t b1 = Ws[kk + tg + 4][ncol0 + nt * 8 + g];
                float* cc = acc[nt];
                asm volatile(
                    "mma.sync.aligned.m16n8k8.row.col.f32.tf32.tf32.f32 "
                    "{%0,%1,%2,%3}, {%4,%5,%6,%7}, {%8,%9}, {%0,%1,%2,%3};"
                    : "+f"(cc[0]), "+f"(cc[1]), "+f"(cc[2]), "+f"(cc[3])
                    : "r"(a0), "r"(a1), "r"(a2), "r"(a3), "r"(b0), "r"(b1));
            }
        }
        __syncthreads();         // all reads of buf done
        issue(i + 2);            // refill this slot

        // epilogue (reads only regs)
        const int tileRow = tiles[i] * 64;
        #pragma unroll
        for (int nt = 0; nt < 5; nt++) {
            int lc = ncol0 + nt * 8 + 2 * tg;
            float b0 = bias ? bias[lc] : 0.f;
            float b1 = bias ? bias[lc + 1] : 0.f;
            float* cc = acc[nt];
            int r0 = tileRow + mw * 16 + g;
            int r1 = r0 + 8;
            float v00 = cc[0] + b0, v01 = cc[1] + b1;
            float v10 = cc[2] + b0, v11 = cc[3] + b1;
            if (LEAKY) {
                v00 = lrelu(v00); v01 = lrelu(v01);
                v10 = lrelu(v10); v11 = lrelu(v11);
            }
            if (ROUND) {
                v00 = rtf(v00); v01 = rtf(v01);
                v10 = rtf(v10); v11 = rtf(v11);
            }
            if (r0 < M)
                *(float2*)(C + (size_t)r0 * ldC + lc) = make_float2(v00, v01);
            if (r1 < M)
                *(float2*)(C + (size_t)r1 * ldC + lc) = make_float2(v10, v11);
        }
    }
}

// ============ projection GEMM (768->32): bulk loads, BK=64, split-K ============
// As[2][128][68] (stride 68 % 32 == 4), Ws[2][64][40] (stride 40 % 32 == 8).
struct ProjArgs {
    const float* A[3];
    const uint32_t* W[3];   // padded [768][40]
    const float* b[3];
    int off[3];
};

#define PJ_AS_BYTES (128 * 68 * 4)      // 34816 per slot
#define PJ_WS_BYTES (64 * 40 * 4)       // 10240 per slot
#define PJ_SMEM (128 + 2 * PJ_AS_BYTES + 2 * PJ_WS_BYTES)   // 90240

__global__ void __launch_bounds__(256) proj_kernel(ProjArgs pa, float* __restrict__ C, int M)
{
    extern __shared__ __align__(16) char sm[];
    const uint32_t sb = smem_u32(sm);
    const uint32_t bar_f0 = sb, bar_f1 = sb + 8;
    const uint32_t as_addr = sb + 128;
    const uint32_t ws_addr = as_addr + 2 * PJ_AS_BYTES;
    float (*As)[128][68] = reinterpret_cast<float (*)[128][68]>(sm + 128);
    uint32_t (*Ws)[64][40] = reinterpret_cast<uint32_t (*)[64][40]>(sm + 128 + 2 * PJ_AS_BYTES);

    const int z = blockIdx.z;
    const float* __restrict__ A = pa.A[z];
    const uint32_t* __restrict__ W = pa.W[z];
    const float* __restrict__ bias = pa.b[z];
    const int cOff = pa.off[z];

    const int t = threadIdx.x;
    const int blockRow = blockIdx.x * 128;
    const int nvalid = (M - blockRow) < 128 ? (M - blockRow) : 128;

    if (t == 0) { MBAR_INIT(bar_f0, 1); MBAR_INIT(bar_f1, 1); }
    __syncthreads();

    const int NCH = 12;   // K=768, BK=64
    auto issue = [&](int c) {
        if (c >= NCH) return;
        const int buf = c & 1;
        const uint32_t bar = buf ? bar_f1 : bar_f0;
        if (t == 0) MBAR_EXPECT(bar, (uint32_t)nvalid * 256 + PJ_WS_BYTES);
        if (t < 128 && t < nvalid) {
            int gr = blockRow + t;
            bulkcp(as_addr + (uint32_t)(buf * 128 + t) * (68 * 4),
                   A + (size_t)gr * 768 + c * 64, 256, bar);
        }
        if (t == 128) {
            bulkcp(ws_addr + (uint32_t)buf * PJ_WS_BYTES,
                   W + (size_t)c * 64 * 40, PJ_WS_BYTES, bar);
        }
    };
    issue(0);
    issue(1);

    const int warp = t >> 5;
    const int lane = t & 31;
    const int mwarp = warp & 3;
    const int kg = warp >> 2;
    const int g = lane >> 2;
    const int tg = lane & 3;
    const int warpRow = mwarp * 32;

    float acc[2][4][4] = {};

    for (int c = 0; c < NCH; c++) {
        MBAR_WAITP((c & 1) ? bar_f1 : bar_f0, (c >> 1) & 1);
        const int buf = c & 1;
        #pragma unroll
        for (int s = 0; s < 4; s++) {
            const int kk = kg * 32 + s * 8;
            uint32_t a[2][4];
            #pragma unroll
            for (int mt = 0; mt < 2; mt++) {
                const int r = warpRow + mt * 16 + g;
                a[mt][0] = f2tf32(As[buf][r][kk + tg]);
                a[mt][1] = f2tf32(As[buf][r + 8][kk + tg]);
                a[mt][2] = f2tf32(As[buf][r][kk + tg + 4]);
                a[mt][3] = f2tf32(As[buf][r + 8][kk + tg + 4]);
            }
            #pragma unroll
            for (int nt = 0; nt < 4; nt++) {
                uint32_t b0 = Ws[buf][kk + tg][nt * 8 + g];
                uint32_t b1 = Ws[buf][kk + tg + 4][nt * 8 + g];
                #pragma unroll
                for (int mt = 0; mt < 2; mt++) {
                    float* cc = acc[mt][nt];
                    asm volatile(
                        "mma.sync.aligned.m16n8k8.row.col.f32.tf32.tf32.f32 "
                        "{%0,%1,%2,%3}, {%4,%5,%6,%7}, {%8,%9}, {%0,%1,%2,%3};"
                        : "+f"(cc[0]), "+f"(cc[1]), "+f"(cc[2]), "+f"(cc[3])
                        : "r"(a[mt][0]), "r"(a[mt][1]), "r"(a[mt][2]), "r"(a[mt][3]),
                          "r"(b0), "r"(b1));
                }
            }
        }
        __syncthreads();     // all reads of buf done
        issue(c + 2);
    }

    // split-K reduce via smem scratch (As area, free now)
    float* scratch = &As[0][0][0];
    if (kg == 1) {
        #pragma unroll
        for (int mt = 0; mt < 2; mt++)
            #pragma unroll
            for (int nt = 0; nt < 4; nt++)
                #pragma unroll
                for (int i = 0; i < 4; i++) {
                    int combo = (mt * 4 + nt) * 4 + i;
                    scratch[combo * 128 + mwarp * 32 + lane] = acc[mt][nt][i];
                }
    }
    __syncthreads();

    if (kg == 0) {
        #pragma unroll
        for (int nt = 0; nt < 4; nt++) {
            int lc = nt * 8 + 2 * tg;
            float b0 = bias[lc];
            float b1 = bias[lc + 1];
            #pragma unroll
            for (int mt = 0; mt < 2; mt++) {
                float* cc = acc[mt][nt];
                int base = ((mt * 4 + nt) * 4) * 128 + mwarp * 32 + lane;
                float v00 = rtf(lrelu(cc[0] + scratch[base]       + b0));
                float v01 = rtf(lrelu(cc[1] + scratch[base + 128] + b1));
                float v10 = rtf(lrelu(cc[2] + scratch[base + 256] + b0));
                float v11 = rtf(lrelu(cc[3] + scratch[base + 384] + b1));
                int r0 = blockRow + warpRow + mt * 16 + g;
                int r1 = r0 + 8;
                if (r0 < M)
                    *(float2*)(C + (size_t)r0 * LD + cOff + lc) = make_float2(v00, v01);
                if (r1 < M)
                    *(float2*)(C + (size_t)r1 * LD + cOff + lc) = make_float2(v10, v11);
            }
        }
    }
}

// ---------------- small feature projections (tf32-rounded outputs) ----------------
__global__ void __launch_bounds__(256) feat_small_kernel(
    const float* __restrict__ np, const float* __restrict__ nc,
    const float* __restrict__ Wnp, const float* __restrict__ bnp,
    const float* __restrict__ Wnc, const float* __restrict__ bnc,
    float* __restrict__ out)
{
    __shared__ float sWnp[6 * 32];
    __shared__ float sWnc[11 * 32];
    __shared__ float sb[64];
    int t = threadIdx.x;
    for (int i = t; i < 192; i += 256) sWnp[i] = Wnp[i];
    for (int i = t; i < 352; i += 256) sWnc[i] = Wnc[i];
    if (t < 32) sb[t] = bnp[t];
    else if (t < 64) sb[t] = bnc[t - 32];
    __syncthreads();

    int node = blockIdx.x * 8 + (t >> 5);
    int lane = t & 31;
    if (node >= NN) return;

    float a = sb[lane], c = sb[32 + lane];
    #pragma unroll
    for (int k = 0; k < 6; k++) a += np[(size_t)node * 6 + k] * sWnp[k * 32 + lane];
    #pragma unroll
    for (int k = 0; k < 11; k++) c += nc[(size_t)node * 11 + k] * sWnc[k * 32 + lane];
    out[(size_t)node * LD + lane] = rtf(lrelu(a));
    out[(size_t)node * LD + 32 + lane] = rtf(lrelu(c));
}

// ---------------- CSR build ----------------
__global__ void zero_deg_kernel() {
    int i = blockIdx.x * blockDim.x + threadIdx.x;
    if (i < NN) g_deg[i] = 0;
}

__global__ void count_deg_kernel(const void* __restrict__ ei, int E) {
    int e = blockIdx.x * blockDim.x + threadIdx.x;
    if (e < E) atomicAdd(&g_deg[edge_val(ei, E + e)], 1);
}

__global__ void scan_kernel() {
    __shared__ int part[1024];
    int t = threadIdx.x;
    const int chunk = (NN + 1023) / 1024;
    int s0 = t * chunk;
    int s1 = s0 + chunk; if (s1 > NN) s1 = NN; if (s0 > NN) s0 = NN;
    int s = 0;
    for (int i = s0; i < s1; i++) s += g_deg[i];
    part[t] = s;
    __syncthreads();
    for (int d = 1; d < 1024; d <<= 1) {
        int v = (t >= d) ? part[t - d] : 0;
        __syncthreads();
        part[t] += v;
        __syncthreads();
    }
    int excl = t ? part[t - 1] : 0;
    for (int i = s0; i < s1; i++) {
        g_offs[i] = excl;
        g_cursor[i] = excl;
        excl += g_deg[i];
    }
    if (t == 1023) g_offs[NN] = part[1023];
}

__global__ void fill_csr_kernel(const void* __restrict__ ei, int E) {
    int e = blockIdx.x * blockDim.x + threadIdx.x;
    if (e < E) {
        int d = edge_val(ei, E + e);
        int p = atomicAdd(&g_cursor[d], 1);
        g_csr[p] = edge_val(ei, e);
    }
}

// -------- fused mean-aggregate + add (float4 gathers, tf32-rounded output) --------
__global__ void __launch_bounds__(256) agg_add_kernel(
    const float* __restrict__ t1, const float* __restrict__ t2,
    float* __restrict__ out)
{
    int w = (blockIdx.x * blockDim.x + threadIdx.x) >> 5;
    int lane = threadIdx.x & 31;
    if (w >= NN) return;
    int beg = g_offs[w], end = g_offs[w + 1];
    const bool tail = lane < 8;

    float4 s0 = make_float4(0.f, 0.f, 0.f, 0.f);
    float4 s1 = make_float4(0.f, 0.f, 0.f, 0.f);

    int e = beg;
    for (; e + 2 <= end; e += 2) {
        const float4* ra = (const float4*)(t1 + (size_t)g_csr[e] * LD);
        const float4* rb = (const float4*)(t1 + (size_t)g_csr[e + 1] * LD);
        float4 va = ra[lane], vb = rb[lane];
        s0.x += va.x + vb.x; s0.y += va.y + vb.y;
        s0.z += va.z + vb.z; s0.w += va.w + vb.w;
        if (tail) {
            float4 ua = ra[32 + lane], ub = rb[32 + lane];
            s1.x += ua.x + ub.x; s1.y += ua.y + ub.y;
            s1.z += ua.z + ub.z; s1.w += ua.w + ub.w;
        }
    }
    if (e < end) {
        const float4* ra = (const float4*)(t1 + (size_t)g_csr[e] * LD);
        float4 va = ra[lane];
        s0.x += va.x; s0.y += va.y; s0.z += va.z; s0.w += va.w;
        if (tail) {
            float4 ua = ra[32 + lane];
            s1.x += ua.x; s1.y += ua.y; s1.z += ua.z; s1.w += ua.w;
        }
    }

    int deg = end - beg;
    float inv = 1.f / (float)(deg > 0 ? deg : 1);
    const float4* b = (const float4*)(t2 + (size_t)w * LD);
    float4* m = (float4*)(out + (size_t)w * LD);

    float4 bv = b[lane];
    float4 o;
    o.x = rtf(s0.x * inv + bv.x);
    o.y = rtf(s0.y * inv + bv.y);
    o.z = rtf(s0.z * inv + bv.z);
    o.w = rtf(s0.w * inv + bv.w);
    m[lane] = o;
    if (tail) {
        float4 bu = b[32 + lane];
        float4 p;
        p.x = rtf(s1.x * inv + bu.x);
        p.y = rtf(s1.y * inv + bu.y);
        p.z = rtf(s1.z * inv + bu.z);
        p.w = rtf(s1.w * inv + bu.w);
        m[32 + lane] = p;
    }
}

// ---------------- final 160->2 head (em has stride 160 in d_out) ----------------
__global__ void __launch_bounds__(256) out2_kernel(
    const float* __restrict__ em, const float* __restrict__ W,
    const float* __restrict__ b, float* __restrict__ out)
{
    __shared__ float sW[320];
    int t = threadIdx.x;
    for (int i = t; i < 320; i += 256) sW[i] = W[i];
    __syncthreads();
    int node = blockIdx.x * 8 + (t >> 5);
    int lane = t & 31;
    if (node >= NN) return;
    float a0 = 0.f, a1 = 0.f;
    #pragma unroll
    for (int c = 0; c < 5; c++) {
        int k = lane + 32 * c;
        float v = em[(size_t)node * HID + k];
        a0 += v * sW[k * 2];
        a1 += v * sW[k * 2 + 1];
    }
    #pragma unroll
    for (int o = 16; o > 0; o >>= 1) {
        a0 += __shfl_down_sync(0xffffffffu, a0, o);
        a1 += __shfl_down_sync(0xffffffffu, a1, o);
    }
    if (lane == 0) {
        out[(size_t)node * 2]     = a0 + b[0];
        out[(size_t)node * 2 + 1] = a1 + b[1];
    }
}

// ---------------- launch ----------------
extern "C" void kernel_launch(void* const* d_in, const int* in_sizes, int n_in,
                              void* d_out, int out_size)
{
    const float* x        = (const float*)d_in[0];
    const void*  ei       = d_in[1];
    const float* num_prop = (const float*)d_in[2];
    const float* num_cat  = (const float*)d_in[3];
    const float* des      = (const float*)d_in[4];
    const float* tw       = (const float*)d_in[5];
    const float* W_des = (const float*)d_in[6];  const float* b_des = (const float*)d_in[7];
    const float* W_tw  = (const float*)d_in[8];  const float* b_tw  = (const float*)d_in[9];
    const float* W_txt = (const float*)d_in[10]; const float* b_txt = (const float*)d_in[11];
    const float* W_np  = (const float*)d_in[12]; const float* b_np  = (const float*)d_in[13];
    const float* W_nc  = (const float*)d_in[14]; const float* b_nc  = (const float*)d_in[15];
    const float* W_in  = (const float*)d_in[16]; const float* b_in  = (const float*)d_in[17];
    const float* W_l   = (const float*)d_in[18]; const float* b_l   = (const float*)d_in[19];
    const float* W_r   = (const float*)d_in[20];
    const float* W_o1  = (const float*)d_in[21]; const float* b_o1  = (const float*)d_in[22];
    const float* W_o2  = (const float*)d_in[23]; const float* b_o2  = (const float*)d_in[24];

    int E = in_sizes[1] / 2;
    if (E > EMAX) E = EMAX;

    float *feat, *h1, *mean, *h2;
    uint32_t* wtf;
    cudaGetSymbolAddress((void**)&feat, g_feat);
    cudaGetSymbolAddress((void**)&h1, g_h1);
    cudaGetSymbolAddress((void**)&mean, g_mean);
    cudaGetSymbolAddress((void**)&h2, g_h2);
    cudaGetSymbolAddress((void**)&wtf, g_wtf);

    float* outp = (float*)d_out;            // [N, 2]
    float* em   = (float*)d_out + 2 * NN;   // [N, 160], stride 160

    // weight preconversion into padded layouts
    WC wa;
    wa.src[0] = W_des; wa.src[1] = W_tw; wa.src[2] = W_txt;
    wa.src[3] = W_in;  wa.src[4] = W_l;  wa.src[5] = W_r; wa.src[6] = W_o1;
    int dense[7] = {24576, 24576, 24576, 25600, 25600, 25600, 25600};
    int dofs[7]  = {0, 30720, 61440, 92160, 119040, 145920, 172800};
    for (int s = 0; s < 7; s++) {
        wa.doff[s] = dofs[s];
        wa.cols[s] = (s < 3) ? 32 : 160;
        wa.ldd[s]  = (s < 3) ? 40 : 168;
    }
    wa.cum[0] = 0;
    for (int s = 0; s < 7; s++) wa.cum[s + 1] = wa.cum[s] + dense[s];
    const uint32_t* tWp_des = wtf + dofs[0];
    const uint32_t* tWp_tw  = wtf + dofs[1];
    const uint32_t* tWp_txt = wtf + dofs[2];
    const uint32_t* tW_in   = wtf + dofs[3];
    const uint32_t* tW_l    = wtf + dofs[4];
    const uint32_t* tW_r    = wtf + dofs[5];
    const uint32_t* tW_o1   = wtf + dofs[6];
    wconv_kernel<<<(wa.cum[7] + 255) / 256, 256>>>(wa);

    static bool attr_done = false;
    if (!attr_done) {
        cudaFuncSetAttribute((const void*)fw_gemm_p<true, true>,
                             cudaFuncAttributeMaxDynamicSharedMemorySize, FW_SMEM);
        cudaFuncSetAttribute((const void*)fw_gemm_p<false, false>,
                             cudaFuncAttributeMaxDynamicSharedMemorySize, FW_SMEM);
        cudaFuncSetAttribute((const void*)fw_gemm_p<true, false>,
                             cudaFuncAttributeMaxDynamicSharedMemorySize, FW_SMEM);
        cudaFuncSetAttribute((const void*)proj_kernel,
                             cudaFuncAttributeMaxDynamicSharedMemorySize, PJ_SMEM);
        attr_done = true;
    }

    dim3 gProj((NN + 127) / 128, 1, 3);
    int gP = 148;
    int gNode8 = (NN + 7) / 8;
    int gEdge = (E + 255) / 256;

    // feature encoder -> g_feat [N, LD] (cols: n|c|d|tw|t), tf32-rounded
    feat_small_kernel<<<gNode8, 256>>>(num_prop, num_cat, W_np, b_np, W_nc, b_nc, feat);
    ProjArgs pa;
    pa.A[0] = des; pa.W[0] = tWp_des; pa.b[0] = b_des; pa.off[0] = 64;
    pa.A[1] = tw;  pa.W[1] = tWp_tw;  pa.b[1] = b_tw;  pa.off[1] = 96;
    pa.A[2] = x;   pa.W[2] = tWp_txt; pa.b[2] = b_txt; pa.off[2] = 128;
    proj_kernel<<<gProj, 256, PJ_SMEM>>>(pa, feat, NN);

    // h1 = rtf(leaky(feat @ W_in + b_in))
    fw_gemm_p<true, true><<<gP, 512, FW_SMEM>>>(feat, tW_in, b_in, h1, LD, NN);

    // CSR build
    detect_kernel<<<1, 256>>>(ei, E);
    zero_deg_kernel<<<(NN + 255) / 256, 256>>>();
    count_deg_kernel<<<gEdge, 256>>>(ei, E);
    scan_kernel<<<1, 1024>>>();
    fill_csr_kernel<<<gEdge, 256>>>(ei, E);

    // conv1: h2 = rtf( mean_nbr(h1 @ W_l) + (h1 @ W_r + b_l) )
    fw_gemm_p<false, false><<<gP, 512, FW_SMEM>>>(h1, tW_l, nullptr, mean, LD, NN);
    fw_gemm_p<false, false><<<gP, 512, FW_SMEM>>>(h1, tW_r, b_l, feat, LD, NN);
    agg_add_kernel<<<gNode8, 256>>>(mean, feat, h2);

    // conv2: h1 = rtf( mean_nbr(h2 @ W_l) + (h2 @ W_r + b_l) )
    fw_gemm_p<false, false><<<gP, 512, FW_SMEM>>>(h2, tW_l, nullptr, mean, LD, NN);
    fw_gemm_p<false, false><<<gP, 512, FW_SMEM>>>(h2, tW_r, b_l, feat, LD, NN);
    agg_add_kernel<<<gNode8, 256>>>(mean, feat, h1);

    // em = leaky(h1 @ W_o1 + b_o1), stride 160, NOT rounded
    fw_gemm_p<true, false><<<gP, 512, FW_SMEM>>>(h1, tW_o1, b_o1, em, HID, NN);

    // out = em @ W_o2 + b_o2
    out2_kernel<<<gNode8, 256>>>(em, W_o2, b_o2, outp);
}